// round 13
// baseline (speedup 1.0000x reference)
#include <cuda_runtime.h>
#include <math.h>

// ---------------- problem dims ----------------
#define TT        8192
#define INDIM     109
#define HDIM      1024
#define GDIM      4096           // 4*HDIM
#define NBLK      128            // LSTM blocks: 128 * 8 elems = 1024
#define EPB       8              // h-elements per block

// ---------------- device scratch ----------------
__device__ float g_xp[TT * GDIM];                 // 128 MB: xp0 projections
__device__ float g_h0hist[TT * HDIM];             // 32 MB h0 history (batch input)
__device__ float g_h1[TT * HDIM];                 // 32 MB layer-1 h history
// publish buffers: [parity][0..1023]=h0, [1024..2047]=h1 (float4-aligned)
__device__ __align__(16) float g_pubH[2][2048];
__device__ __align__(16) unsigned g_flag[NBLK];   // packed u32 flags (4 lines)

// ---------------- small helpers ----------------
__device__ __forceinline__ unsigned long long fma2(unsigned long long a,
                                                   unsigned long long b,
                                                   unsigned long long c) {
    unsigned long long d;
    asm("fma.rn.f32x2 %0, %1, %2, %3;" : "=l"(d) : "l"(a), "l"(b), "l"(c));
    return d;
}
__device__ __forceinline__ float2 unpack2(unsigned long long v) {
    float2 f;
    asm("mov.b64 {%0,%1}, %2;" : "=f"(f.x), "=f"(f.y) : "l"(v));
    return f;
}
__device__ __forceinline__ float fast_tanh(float x) {
    float e = __expf(-2.f * x);
    return fmaf(2.f, __fdividef(1.f, 1.f + e), -1.f);
}
__device__ __forceinline__ float warp_red4(float s) {
#pragma unroll
    for (int off = 16; off; off >>= 1)
        s += __shfl_xor_sync(0xffffffffu, s, off);
    return s;
}
__device__ __forceinline__ float dot4acc(float4 wv, float4 hv, float a) {
    a = fmaf(wv.x, hv.x, a);
    a = fmaf(wv.y, hv.y, a);
    a = fmaf(wv.z, hv.z, a);
    a = fmaf(wv.w, hv.w, a);
    return a;
}

__global__ void reset_state_kernel() {
    int i = threadIdx.x;                  // 1024 threads
    float* p = &g_pubH[0][0];             // 4096 floats total
#pragma unroll
    for (int q = 0; q < 4; q++) p[i + 1024 * q] = 0.f;
    if (i < NBLK) g_flag[i] = 0u;
}

// ---------------- xp0: [T,109] @ [4096,109]^T + bias ----------------
__global__ __launch_bounds__(256) void gemm_xproj_small(
    const float* __restrict__ A,      // [T][109]
    const float* __restrict__ B,      // [4096][109]
    const float* __restrict__ bias1,
    const float* __restrict__ bias2)
{
    __shared__ float sA[64][113];
    __shared__ float sB[32][113];
    int t0 = blockIdx.x * 64;
    int r0 = blockIdx.y * 32;
    int tid = threadIdx.x;
    int tx = tid & 15;
    int ty = tid >> 4;

    for (int idx = tid; idx < 64 * INDIM; idx += 256) {
        int row = idx / INDIM, k = idx - row * INDIM;
        sA[row][k] = A[(size_t)(t0 + row) * INDIM + k];
    }
    for (int idx = tid; idx < 32 * INDIM; idx += 256) {
        int row = idx / INDIM, k = idx - row * INDIM;
        sB[row][k] = B[(size_t)(r0 + row) * INDIM + k];
    }
    __syncthreads();

    float acc[4][2];
#pragma unroll
    for (int i = 0; i < 4; i++)
#pragma unroll
        for (int j = 0; j < 2; j++) acc[i][j] = 0.f;

    for (int k = 0; k < INDIM; k++) {
        float a[4], b[2];
#pragma unroll
        for (int i = 0; i < 4; i++) a[i] = sA[ty * 4 + i][k];
#pragma unroll
        for (int j = 0; j < 2; j++) b[j] = sB[tx * 2 + j][k];
#pragma unroll
        for (int i = 0; i < 4; i++)
#pragma unroll
            for (int j = 0; j < 2; j++) acc[i][j] = fmaf(a[i], b[j], acc[i][j]);
    }

#pragma unroll
    for (int j = 0; j < 2; j++) {
        int r = r0 + tx * 2 + j;
        float bs = __ldg(&bias1[r]) + __ldg(&bias2[r]);
#pragma unroll
        for (int i = 0; i < 4; i++) {
            int t = t0 + ty * 4 + i;
            g_xp[(size_t)t * GDIM + r] = acc[i][j] + bs;
        }
    }
}

// ---------------- fused 2-layer LSTM, batched xp1 (C=2, lag 4) ------------
// 128 blocks x 256 threads. Block b owns h0/h1 elems [8b, 8b+8).
// Warp w owns element e = 8b+w of both layers.
// Step s computes h0_s (layer 0) and h1_{s-4} (layer 1).
//   pre-poll  : batch xp1 phase. Batch B covers u in {2B, 2B+1}; computed
//               over steps {2B+2, 2B+3} (phase p=(s-2)&1 covers k-chunks
//               4p..4p+3). Reads wi (SMEM, ONCE per 2 timesteps) and
//               g_h0hist (L2, ldcg; ordered by flag acquire since hist is
//               stored pre-release). End of phase 1: reduce 8 vals ->
//               sXp1[B&1]. First use at s = u+4.
//   poll      : R5 barrier — warp 0, one ld.acquire.v4 per lane, 4 lines
//   stage     : h0_{s-1}, h1_{s-5} -> SMEM (ldcg, parity s&1)
//   post-poll : a0 = W_hh0(RF) @ h0_{s-1}; a1 = W_hh1(SMEM+RF) @ h1_{s-5};
//               reduce; gates (xp1 from sXp1); publish (incl. h0hist,
//               pre-release); release.
// SMEM: sWih1 131072 | sWhh1 81920 | sH0 4096 | sH1 4096 | sPub 64 | sXp1 512
#define FUS_SMEM (131072 + 81920 + 4096 + 4096 + 64 + 512)

__global__ __launch_bounds__(256, 1) void lstm_fused_kernel(
    const float* __restrict__ Whh0,   // [4096][1024]
    const float* __restrict__ Wih1,   // [4096][1024]
    const float* __restrict__ Whh1,   // [4096][1024]
    const float* __restrict__ b_ih1,
    const float* __restrict__ b_hh1)
{
    extern __shared__ char smem[];
    float4* sWih1 = (float4*)(smem);                            // 32 rows x 256 f4
    float4* sWhh1 = (float4*)(smem + 131072);                   // 32 rows x 160 f4
    float4* sH0   = (float4*)(smem + 131072 + 81920);           // 256 f4
    float4* sH1   = (float4*)(smem + 131072 + 81920 + 4096);    // 256 f4
    float*  sPub  = (float*)(smem + 131072 + 81920 + 8192);     // 16 floats
    float*  sXp1  = (float*)(smem + 131072 + 81920 + 8192 + 64);// [2][2][4][8]

    int b   = blockIdx.x;
    int tid = threadIdx.x;
    int w   = tid >> 5;
    int l   = tid & 31;
    int e   = (b << 3) + w;
    int gl  = l & 3;                  // gate index for lanes 0..7

    // ---- RF weights ----
    ulonglong2 W0[4][8];              // W_hh0, full rows
    ulonglong2 W1r[4][3];             // W_hh1, k=5..7 (cols 640..1023)
#pragma unroll
    for (int g = 0; g < 4; g++) {
        const ulonglong2* r0p =
            (const ulonglong2*)(Whh0 + (size_t)((g << 10) + e) * HDIM);
        const ulonglong2* r1p =
            (const ulonglong2*)(Whh1 + (size_t)((g << 10) + e) * HDIM);
#pragma unroll
        for (int k = 0; k < 8; k++) W0[g][k] = r0p[l + 32 * k];
#pragma unroll
        for (int k = 0; k < 3; k++) W1r[g][k] = r1p[l + 32 * (5 + k)];
    }

    // ---- SMEM weights (cooperative) ----
    for (int idx = tid; idx < 32 * 256; idx += 256) {
        int rl = idx >> 8, c4 = idx & 255;
        int g = rl >> 3, ww = rl & 7;
        sWih1[idx] = ((const float4*)(Wih1 +
            (size_t)((g << 10) + (b << 3) + ww) * HDIM))[c4];
    }
    for (int idx = tid; idx < 32 * 160; idx += 256) {
        int rl = idx / 160, c4 = idx - rl * 160;
        int g = rl >> 3, ww = rl & 7;
        sWhh1[idx] = ((const float4*)(Whh1 +
            (size_t)((g << 10) + (b << 3) + ww) * HDIM))[c4];
    }

    // layer-1 bias sum on lanes 4..7 (lane 4+g holds gate g's bias)
    float bs1v = 0.f;
    if (l >= 4 && l < 8) {
        int r = (gl << 10) + e;
        bs1v = __ldg(&b_ih1[r]) + __ldg(&b_hh1[r]);
    }

    // init SMEM buffers
    sH0[tid] = make_float4(0.f, 0.f, 0.f, 0.f);
    sH1[tid] = make_float4(0.f, 0.f, 0.f, 0.f);
    if (tid < 16) sPub[tid] = 0.f;
    if (tid < 128) sXp1[tid] = 0.f;
    float c0 = 0.f, c1 = 0.f;         // c0 on lane 0, c1 on lane 4
    float acc_xp[4][2];               // batch accumulators (this thread's 32 cols)
#pragma unroll
    for (int g = 0; g < 4; g++) { acc_xp[g][0] = 0.f; acc_xp[g][1] = 0.f; }
    __syncthreads();

    const uint4* flags4 = (const uint4*)g_flag;

    // prefetch xp0 for s=0: lane g in 0..3 loads gate g
    float xv = 0.f;
    if (l < 4) xv = __ldg(g_xp + (gl << 10) + e);

    const ulonglong2* H0 = (const ulonglong2*)sH0;
    const ulonglong2* H1 = (const ulonglong2*)sH1;
    const ulonglong2* wh = (const ulonglong2*)sWhh1;

    for (int s = 0; s <= TT + 3; s++) {
        // ===== pre-poll: xp1 batch phase =====
        if (s >= 2 && s < TT + 2) {
            int B = (s - 2) >> 1;
            int p = (s - 2) & 1;
            const float4* hist =
                (const float4*)(g_h0hist + (size_t)(2 * B) * HDIM);
            // issue all 8 hist L2 loads first (MLP hides latency)
            float4 ha[4], hb[4];
#pragma unroll
            for (int kk = 0; kk < 4; kk++) {
                int c4 = 32 * (4 * p + kk) + l;
                ha[kk] = __ldcg(hist + c4);           // u = 2B
                hb[kk] = __ldcg(hist + 256 + c4);     // u = 2B+1
            }
#pragma unroll
            for (int kk = 0; kk < 4; kk++) {
                int k = 4 * p + kk;
#pragma unroll
                for (int g = 0; g < 4; g++) {
                    float4 wv = sWih1[(size_t)((g << 3) + w) * 256 + 32 * k + l];
                    acc_xp[g][0] = dot4acc(wv, ha[kk], acc_xp[g][0]);
                    acc_xp[g][1] = dot4acc(wv, hb[kk], acc_xp[g][1]);
                }
            }
            if (p == 1) {
                // batch complete: reduce 8 values, store to sXp1[B&1]
                float bd[8];
#pragma unroll
                for (int j = 0; j < 8; j++)
                    bd[j] = warp_red4(acc_xp[j >> 1][j & 1]);
                if (l < 8)
                    sXp1[((B & 1) << 6) + ((l & 1) << 5) + ((l >> 1) << 3) + w]
                        = bd[l];
#pragma unroll
                for (int g = 0; g < 4; g++) {
                    acc_xp[g][0] = 0.f; acc_xp[g][1] = 0.f;
                }
            }
        }

        // prefetch xp0 for next step (consumed one step later)
        float nxv = 0.f;
        if (l < 4 && s + 1 < TT)
            nxv = __ldg(g_xp + (size_t)(s + 1) * GDIM + (gl << 10) + e);

        // ===== poll (R5 barrier, byte-for-byte) =====
        if (s) {
            if (w == 0) {
                unsigned need = (unsigned)s;
                bool ok;
                do {
                    uint4 v;
                    asm volatile(
                        "ld.acquire.gpu.global.v4.u32 {%0,%1,%2,%3}, [%4];"
                        : "=r"(v.x), "=r"(v.y), "=r"(v.z), "=r"(v.w)
                        : "l"(flags4 + l) : "memory");
                    ok = v.x >= need && v.y >= need && v.z >= need && v.w >= need;
                } while (!__all_sync(0xffffffffu, ok));
            }
        }
        __syncthreads();

        // ===== stage h0_{s-1}, h1_{s-5} =====
        {
            const float4* pub4 = (const float4*)g_pubH[s & 1];
            sH0[tid] = __ldcg(pub4 + tid);
            sH1[tid] = __ldcg(pub4 + 256 + tid);
        }
        __syncthreads();

        // ===== post-poll: a0 = W_hh0 @ h0_{s-1};  a1 = W_hh1 @ h1_{s-5} =====
        unsigned long long a0[4][2], a1[4][2];
#pragma unroll
        for (int g = 0; g < 4; g++) {
            a0[g][0] = 0ull; a0[g][1] = 0ull;
            a1[g][0] = 0ull; a1[g][1] = 0ull;
        }
#pragma unroll
        for (int k = 0; k < 8; k++) {
            ulonglong2 h0v = H0[32 * k + l];
            ulonglong2 h1v = H1[32 * k + l];
#pragma unroll
            for (int g = 0; g < 4; g++) {
                a0[g][0] = fma2(W0[g][k].x, h0v.x, a0[g][0]);
                a0[g][1] = fma2(W0[g][k].y, h0v.y, a0[g][1]);
                ulonglong2 wv1 = (k < 5)
                    ? wh[(size_t)((g << 3) + w) * 160 + 32 * k + l]
                    : W1r[g][k - 5];
                a1[g][0] = fma2(wv1.x, h1v.x, a1[g][0]);
                a1[g][1] = fma2(wv1.y, h1v.y, a1[g][1]);
            }
        }

        // xor-shuffle reduce: EVERY lane ends with the full dot products
        float dot0[4], dot1[4];
#pragma unroll
        for (int g = 0; g < 4; g++) {
            float2 lo0 = unpack2(a0[g][0]);
            float2 hi0 = unpack2(a0[g][1]);
            dot0[g] = warp_red4((lo0.x + lo0.y) + (hi0.x + hi0.y));
            float2 lo1 = unpack2(a1[g][0]);
            float2 hi1 = unpack2(a1[g][1]);
            dot1[g] = warp_red4((lo1.x + lo1.y) + (hi1.x + hi1.y));
        }

        // ===== parallel gate activations (lanes 0..7, branch-free) =====
        float xp1v = 0.f;
        if (l >= 4 && l < 8 && s >= 4) {
            int sm4 = s - 4;
            xp1v = sXp1[(((sm4 >> 1) & 1) << 6) + ((sm4 & 1) << 5)
                        + (gl << 3) + w];
        }
        float pre = ((l & 4) ? dot1[gl] + bs1v + xp1v : dot0[gl] + xv);
        float kx  = (gl == 2) ? 2.f * pre : pre;        // tanh needs 2x
        float ev  = __expf(-kx);
        float rv  = __fdividef(1.f, 1.f + ev);
        float act = (gl == 2) ? fmaf(2.f, rv, -1.f) : rv;

        int base = l & 4;
        float iv = __shfl_sync(0xffffffffu, act, base + 0);
        float fv = __shfl_sync(0xffffffffu, act, base + 1);
        float gv = __shfl_sync(0xffffffffu, act, base + 2);
        float ov = __shfl_sync(0xffffffffu, act, base + 3);

        float h1n = 0.f;
        if (l == 0 && s < TT) {                   // layer 0: h0_s
            c0 = fmaf(fv, c0, iv * gv);
            sPub[w] = ov * fast_tanh(c0);
        }
        if (l == 4 && s >= 4) {                   // layer 1: h1_{s-4}
            c1 = fmaf(fv, c1, iv * gv);
            h1n = ov * fast_tanh(c1);
            sPub[8 + w] = h1n;
        }
        __syncthreads();

        // ===== publish (tid 0 only -> release covers its own stores) =====
        if (tid == 0) {
            float4 p0 = *(const float4*)&sPub[0];
            float4 p1 = *(const float4*)&sPub[4];
            float4 q0 = *(const float4*)&sPub[8];
            float4 q1 = *(const float4*)&sPub[12];
            float4* dst = (float4*)g_pubH[(s + 1) & 1];
            __stcg(dst + 2 * b,           p0);
            __stcg(dst + 2 * b + 1,       p1);
            __stcg(dst + 256 + 2 * b,     q0);
            __stcg(dst + 256 + 2 * b + 1, q1);
            if (s < TT) {                 // h0 history, PRE-release (ordered)
                float4* hd = (float4*)&g_h0hist[(size_t)s * HDIM + (b << 3)];
                __stcg(hd,     p0);
                __stcg(hd + 1, p1);
            }
            asm volatile("st.release.gpu.global.u32 [%0], %1;"
                         :: "l"(&g_flag[b]), "r"((unsigned)(s + 1)) : "memory");
        }

        // ===== h1 history (off the release path, lane 4) =====
        if (l == 4 && s >= 4) {
            __stcg(&g_h1[(size_t)(s - 4) * HDIM + e], h1n);
        }

        xv = nxv;
    }
}

// ---------------- FC + log_softmax ----------------
__global__ __launch_bounds__(128) void fc_logsoftmax_kernel(
    const float* __restrict__ fcw,    // [109][1024]
    const float* __restrict__ fcb,    // [109]
    float* __restrict__ out)          // [T][109]
{
    __shared__ float sH[8 * 1024];
    __shared__ float sL[8][112];
    __shared__ float sLse[8];
    int t0 = blockIdx.x * 8;
    int tid = threadIdx.x;

    const float4* hg = (const float4*)(g_h1 + (size_t)t0 * HDIM);
    float4* sH4 = (float4*)sH;
#pragma unroll
    for (int q = 0; q < 16; q++) sH4[tid + 128 * q] = __ldg(hg + tid + 128 * q);
    __syncthreads();

    if (tid < INDIM) {
        float acc[8];
#pragma unroll
        for (int i = 0; i < 8; i++) acc[i] = 0.f;
        const float4* w4 = (const float4*)(fcw + (size_t)tid * HDIM);
        for (int k4 = 0; k4 < 256; k4++) {
            float4 w = __ldg(w4 + k4);
#pragma unroll
            for (int tt = 0; tt < 8; tt++) {
                float4 hv = sH4[tt * 256 + k4];
                acc[tt] = fmaf(w.x, hv.x,
                          fmaf(w.y, hv.y,
                          fmaf(w.z, hv.z,
                          fmaf(w.w, hv.w, acc[tt]))));
            }
        }
        float bb = __ldg(&fcb[tid]);
#pragma unroll
        for (int tt = 0; tt < 8; tt++) sL[tt][tid] = acc[tt] + bb;
    }
    __syncthreads();

    if (tid < 8) {
        float m = -1e30f;
        for (int n = 0; n < INDIM; n++) m = fmaxf(m, sL[tid][n]);
        float s = 0.f;
        for (int n = 0; n < INDIM; n++) s += expf(sL[tid][n] - m);
        sLse[tid] = m + logf(s);
    }
    __syncthreads();

    for (int idx = tid; idx < 8 * INDIM; idx += 128) {
        int tt = idx / INDIM, n = idx - tt * INDIM;
        out[(size_t)(t0 + tt) * INDIM + n] = sL[tt][n] - sLse[tt];
    }
}

// ---------------- launcher ----------------
extern "C" void kernel_launch(void* const* d_in, const int* in_sizes, int n_in,
                              void* d_out, int out_size) {
    const float* input = (const float*)d_in[0];
    const float* W_ih0 = (const float*)d_in[1];
    const float* W_hh0 = (const float*)d_in[2];
    const float* b_ih0 = (const float*)d_in[3];
    const float* b_hh0 = (const float*)d_in[4];
    const float* W_ih1 = (const float*)d_in[5];
    const float* W_hh1 = (const float*)d_in[6];
    const float* b_ih1 = (const float*)d_in[7];
    const float* b_hh1 = (const float*)d_in[8];
    const float* fc_w  = (const float*)d_in[9];
    const float* fc_b  = (const float*)d_in[10];
    float* out = (float*)d_out;

    cudaFuncSetAttribute(lstm_fused_kernel,
                         cudaFuncAttributeMaxDynamicSharedMemorySize, FUS_SMEM);

    // xp0 = input @ W_ih0^T + b_ih0 + b_hh0
    gemm_xproj_small<<<dim3(TT / 64, GDIM / 32), 256>>>(input, W_ih0, b_ih0, b_hh0);

    // fused 2-layer recurrence -> g_h1
    reset_state_kernel<<<1, 1024>>>();
    lstm_fused_kernel<<<NBLK, 256, FUS_SMEM>>>(W_hh0, W_ih1, W_hh1, b_ih1, b_hh1);

    // logits + log_softmax
    fc_logsoftmax_kernel<<<TT / 8, 128>>>(fc_w, fc_b, out);
}

// round 14
// speedup vs baseline: 1.2953x; 1.2953x over previous
#include <cuda_runtime.h>
#include <math.h>

// ---------------- problem dims ----------------
#define TT        8192
#define INDIM     109
#define HDIM      1024
#define GDIM      4096           // 4*HDIM
#define NBLK      128            // LSTM blocks: 128 * 8 elems = 1024
#define EPB       8              // h-elements per block

// ---------------- device scratch ----------------
__device__ float g_xp[TT * GDIM];                 // 128 MB: xp0 projections
__device__ float g_h0hist[TT * HDIM];             // 32 MB h0 history (batch input)
__device__ float g_h1[TT * HDIM];                 // 32 MB layer-1 h history
// publish buffers: [parity][0..1023]=h0, [1024..2047]=h1 (float4-aligned)
__device__ __align__(16) float g_pubH[2][2048];
__device__ __align__(16) unsigned g_flag[NBLK];   // packed u32 flags (4 lines)

// ---------------- small helpers ----------------
__device__ __forceinline__ unsigned long long fma2(unsigned long long a,
                                                   unsigned long long b,
                                                   unsigned long long c) {
    unsigned long long d;
    asm("fma.rn.f32x2 %0, %1, %2, %3;" : "=l"(d) : "l"(a), "l"(b), "l"(c));
    return d;
}
__device__ __forceinline__ float2 unpack2(unsigned long long v) {
    float2 f;
    asm("mov.b64 {%0,%1}, %2;" : "=f"(f.x), "=f"(f.y) : "l"(v));
    return f;
}
__device__ __forceinline__ float fast_tanh(float x) {
    float e = __expf(-2.f * x);
    return fmaf(2.f, __fdividef(1.f, 1.f + e), -1.f);
}
__device__ __forceinline__ float warp_red4(float s) {
#pragma unroll
    for (int off = 16; off; off >>= 1)
        s += __shfl_xor_sync(0xffffffffu, s, off);
    return s;
}
__device__ __forceinline__ float red_ull2(unsigned long long a,
                                          unsigned long long b) {
    float2 lo = unpack2(a), hi = unpack2(b);
    return warp_red4((lo.x + lo.y) + (hi.x + hi.y));
}

__global__ void reset_state_kernel() {
    int i = threadIdx.x;                  // 1024 threads
    float* p = &g_pubH[0][0];             // 4096 floats total
#pragma unroll
    for (int q = 0; q < 4; q++) p[i + 1024 * q] = 0.f;
    if (i < NBLK) g_flag[i] = 0u;
}

// ---------------- xp0: [T,109] @ [4096,109]^T + bias ----------------
__global__ __launch_bounds__(256) void gemm_xproj_small(
    const float* __restrict__ A,      // [T][109]
    const float* __restrict__ B,      // [4096][109]
    const float* __restrict__ bias1,
    const float* __restrict__ bias2)
{
    __shared__ float sA[64][113];
    __shared__ float sB[32][113];
    int t0 = blockIdx.x * 64;
    int r0 = blockIdx.y * 32;
    int tid = threadIdx.x;
    int tx = tid & 15;
    int ty = tid >> 4;

    for (int idx = tid; idx < 64 * INDIM; idx += 256) {
        int row = idx / INDIM, k = idx - row * INDIM;
        sA[row][k] = A[(size_t)(t0 + row) * INDIM + k];
    }
    for (int idx = tid; idx < 32 * INDIM; idx += 256) {
        int row = idx / INDIM, k = idx - row * INDIM;
        sB[row][k] = B[(size_t)(r0 + row) * INDIM + k];
    }
    __syncthreads();

    float acc[4][2];
#pragma unroll
    for (int i = 0; i < 4; i++)
#pragma unroll
        for (int j = 0; j < 2; j++) acc[i][j] = 0.f;

    for (int k = 0; k < INDIM; k++) {
        float a[4], b[2];
#pragma unroll
        for (int i = 0; i < 4; i++) a[i] = sA[ty * 4 + i][k];
#pragma unroll
        for (int j = 0; j < 2; j++) b[j] = sB[tx * 2 + j][k];
#pragma unroll
        for (int i = 0; i < 4; i++)
#pragma unroll
            for (int j = 0; j < 2; j++) acc[i][j] = fmaf(a[i], b[j], acc[i][j]);
    }

#pragma unroll
    for (int j = 0; j < 2; j++) {
        int r = r0 + tx * 2 + j;
        float bs = __ldg(&bias1[r]) + __ldg(&bias2[r]);
#pragma unroll
        for (int i = 0; i < 4; i++) {
            int t = t0 + ty * 4 + i;
            g_xp[(size_t)t * GDIM + r] = acc[i][j] + bs;
        }
    }
}

// ---------------- fused 2-layer LSTM, batched xp1 v2 (lag 4) --------------
// 128 blocks x 256 threads. Block b owns h0/h1 elems [8b, 8b+8).
// Warp w owns element e = 8b+w of both layers.
// Step s computes h0_s (layer 0) and h1_{s-4} (layer 1).
//   pre-poll (EVEN s only): full 2-timestep xp1 batch for u0=s-3, u1=s-2.
//     Visibility: pre-poll at step s has acquired flags >= s-1 (previous
//     iteration's poll) => hist up to h0_{s-2} visible. u0,u1 <= s-2. SAFE.
//     stage hist[u0],hist[u1] -> sHA/sHB (bar); one weight pass accumulates
//     BOTH timesteps (weights read once per 2 steps); reduce; store to
//     sXp1[u&3]. Accumulators die inside the step (no cross-poll liveness).
//   poll      : R5 barrier — warp 0, one ld.acquire.v4 per lane, 4 lines
//   stage     : h0_{s-1}, h1_{s-5} -> SMEM (ldcg, parity s&1)
//   post-poll : a0 = W_hh0(RF) @ h0_{s-1}; a1 = W_hh1(SMEM+RF) @ h1_{s-5};
//               reduce; gates (xp1 from sXp1[(s-4)&3]); publish (incl.
//               h0hist, pre-release); release.
// SMEM: sWih1 131072 | sWhh1 81920 | sH0 4096 | sH1 4096 | sHA 4096 |
//       sHB 4096 | sPub 64 | sXp1 512   = 229,952 B
#define FUS_SMEM (131072 + 81920 + 4096 + 4096 + 4096 + 4096 + 64 + 512)

__global__ __launch_bounds__(256, 1) void lstm_fused_kernel(
    const float* __restrict__ Whh0,   // [4096][1024]
    const float* __restrict__ Wih1,   // [4096][1024]
    const float* __restrict__ Whh1,   // [4096][1024]
    const float* __restrict__ b_ih1,
    const float* __restrict__ b_hh1)
{
    extern __shared__ char smem[];
    float4* sWih1 = (float4*)(smem);                            // 32 rows x 256 f4
    float4* sWhh1 = (float4*)(smem + 131072);                   // 32 rows x 160 f4
    float4* sH0   = (float4*)(smem + 131072 + 81920);           // 256 f4
    float4* sH1   = (float4*)(smem + 131072 + 81920 + 4096);    // 256 f4
    float4* sHA   = (float4*)(smem + 131072 + 81920 + 8192);    // 256 f4
    float4* sHB   = (float4*)(smem + 131072 + 81920 + 12288);   // 256 f4
    float*  sPub  = (float*)(smem + 131072 + 81920 + 16384);    // 16 floats
    float*  sXp1  = (float*)(smem + 131072 + 81920 + 16384 + 64); // [4][32]

    int b   = blockIdx.x;
    int tid = threadIdx.x;
    int w   = tid >> 5;
    int l   = tid & 31;
    int e   = (b << 3) + w;
    int gl  = l & 3;                  // gate index for lanes 0..7

    // ---- RF weights ----
    ulonglong2 W0[4][8];              // W_hh0, full rows
    ulonglong2 W1r[4][3];             // W_hh1, k=5..7 (cols 640..1023)
#pragma unroll
    for (int g = 0; g < 4; g++) {
        const ulonglong2* r0p =
            (const ulonglong2*)(Whh0 + (size_t)((g << 10) + e) * HDIM);
        const ulonglong2* r1p =
            (const ulonglong2*)(Whh1 + (size_t)((g << 10) + e) * HDIM);
#pragma unroll
        for (int k = 0; k < 8; k++) W0[g][k] = r0p[l + 32 * k];
#pragma unroll
        for (int k = 0; k < 3; k++) W1r[g][k] = r1p[l + 32 * (5 + k)];
    }

    // ---- SMEM weights (cooperative) ----
    for (int idx = tid; idx < 32 * 256; idx += 256) {
        int rl = idx >> 8, c4 = idx & 255;
        int g = rl >> 3, ww = rl & 7;
        sWih1[idx] = ((const float4*)(Wih1 +
            (size_t)((g << 10) + (b << 3) + ww) * HDIM))[c4];
    }
    for (int idx = tid; idx < 32 * 160; idx += 256) {
        int rl = idx / 160, c4 = idx - rl * 160;
        int g = rl >> 3, ww = rl & 7;
        sWhh1[idx] = ((const float4*)(Whh1 +
            (size_t)((g << 10) + (b << 3) + ww) * HDIM))[c4];
    }

    // layer-1 bias sum on lanes 4..7 (lane 4+g holds gate g's bias)
    float bs1v = 0.f;
    if (l >= 4 && l < 8) {
        int r = (gl << 10) + e;
        bs1v = __ldg(&b_ih1[r]) + __ldg(&b_hh1[r]);
    }

    // init SMEM buffers
    sH0[tid] = make_float4(0.f, 0.f, 0.f, 0.f);
    sH1[tid] = make_float4(0.f, 0.f, 0.f, 0.f);
    if (tid < 16) sPub[tid] = 0.f;
    if (tid < 128) sXp1[tid] = 0.f;
    float c0 = 0.f, c1 = 0.f;         // c0 on lane 0, c1 on lane 4
    __syncthreads();

    const uint4* flags4 = (const uint4*)g_flag;

    // prefetch xp0 for s=0: lane g in 0..3 loads gate g
    float xv = 0.f;
    if (l < 4) xv = __ldg(g_xp + (gl << 10) + e);

    const ulonglong2* H0 = (const ulonglong2*)sH0;
    const ulonglong2* H1 = (const ulonglong2*)sH1;
    const ulonglong2* wi = (const ulonglong2*)sWih1;
    const ulonglong2* wh = (const ulonglong2*)sWhh1;

    for (int s = 0; s <= TT + 3; s++) {
        // ===== pre-poll (even s): full xp1 batch for u0=s-3, u1=s-2 =====
        if (!(s & 1) && s >= 2 && s <= TT + 2) {
            int u0 = s - 3;               // may be -1 at s=2
            int u1 = s - 2;               // may be TT at s=TT+2
            int u0c = u0 < 0 ? 0 : u0;
            int u1c = u1 >= TT ? TT - 1 : u1;
            // stage both hist vectors into SMEM (L2 -> SMEM once per CTA)
            sHA[tid] = __ldcg((const float4*)(g_h0hist + (size_t)u0c * HDIM) + tid);
            sHB[tid] = __ldcg((const float4*)(g_h0hist + (size_t)u1c * HDIM) + tid);
            __syncthreads();

            const ulonglong2* HA = (const ulonglong2*)sHA;
            const ulonglong2* HB = (const ulonglong2*)sHB;
            unsigned long long aA[4][2], aB[4][2];
#pragma unroll
            for (int g = 0; g < 4; g++) {
                aA[g][0] = 0ull; aA[g][1] = 0ull;
                aB[g][0] = 0ull; aB[g][1] = 0ull;
            }
#pragma unroll
            for (int k = 0; k < 8; k++) {
                ulonglong2 ha = HA[32 * k + l];
                ulonglong2 hb = HB[32 * k + l];
#pragma unroll
                for (int g = 0; g < 4; g++) {
                    ulonglong2 wv = wi[(size_t)((g << 3) + w) * 256 + 32 * k + l];
                    aA[g][0] = fma2(wv.x, ha.x, aA[g][0]);
                    aA[g][1] = fma2(wv.y, ha.y, aA[g][1]);
                    aB[g][0] = fma2(wv.x, hb.x, aB[g][0]);
                    aB[g][1] = fma2(wv.y, hb.y, aB[g][1]);
                }
            }
            float dA[4], dB[4];
#pragma unroll
            for (int g = 0; g < 4; g++) {
                dA[g] = red_ull2(aA[g][0], aA[g][1]);
                dB[g] = red_ull2(aB[g][0], aB[g][1]);
            }
            // store: lanes 0-3 -> u0 (gate l), lanes 4-7 -> u1 (gate l-4)
            if (l < 4 && u0 >= 0)
                sXp1[((u0 & 3) << 5) + (gl << 3) + w] = dA[gl];
            if (l >= 4 && l < 8 && u1 < TT)
                sXp1[((u1 & 3) << 5) + (gl << 3) + w] = dB[gl];
        }

        // prefetch xp0 for next step (consumed one step later)
        float nxv = 0.f;
        if (l < 4 && s + 1 < TT)
            nxv = __ldg(g_xp + (size_t)(s + 1) * GDIM + (gl << 10) + e);

        // ===== poll (R5 barrier, byte-for-byte) =====
        if (s) {
            if (w == 0) {
                unsigned need = (unsigned)s;
                bool ok;
                do {
                    uint4 v;
                    asm volatile(
                        "ld.acquire.gpu.global.v4.u32 {%0,%1,%2,%3}, [%4];"
                        : "=r"(v.x), "=r"(v.y), "=r"(v.z), "=r"(v.w)
                        : "l"(flags4 + l) : "memory");
                    ok = v.x >= need && v.y >= need && v.z >= need && v.w >= need;
                } while (!__all_sync(0xffffffffu, ok));
            }
        }
        __syncthreads();

        // ===== stage h0_{s-1}, h1_{s-5} =====
        {
            const float4* pub4 = (const float4*)g_pubH[s & 1];
            sH0[tid] = __ldcg(pub4 + tid);
            sH1[tid] = __ldcg(pub4 + 256 + tid);
        }
        __syncthreads();

        // ===== post-poll: a0 = W_hh0 @ h0_{s-1};  a1 = W_hh1 @ h1_{s-5} =====
        unsigned long long a0[4][2], a1[4][2];
#pragma unroll
        for (int g = 0; g < 4; g++) {
            a0[g][0] = 0ull; a0[g][1] = 0ull;
            a1[g][0] = 0ull; a1[g][1] = 0ull;
        }
#pragma unroll
        for (int k = 0; k < 8; k++) {
            ulonglong2 h0v = H0[32 * k + l];
            ulonglong2 h1v = H1[32 * k + l];
#pragma unroll
            for (int g = 0; g < 4; g++) {
                a0[g][0] = fma2(W0[g][k].x, h0v.x, a0[g][0]);
                a0[g][1] = fma2(W0[g][k].y, h0v.y, a0[g][1]);
                ulonglong2 wv1 = (k < 5)
                    ? wh[(size_t)((g << 3) + w) * 160 + 32 * k + l]
                    : W1r[g][k - 5];
                a1[g][0] = fma2(wv1.x, h1v.x, a1[g][0]);
                a1[g][1] = fma2(wv1.y, h1v.y, a1[g][1]);
            }
        }

        // xor-shuffle reduce: EVERY lane ends with the full dot products
        float dot0[4], dot1[4];
#pragma unroll
        for (int g = 0; g < 4; g++) {
            dot0[g] = red_ull2(a0[g][0], a0[g][1]);
            dot1[g] = red_ull2(a1[g][0], a1[g][1]);
        }

        // ===== parallel gate activations (lanes 0..7, branch-free) =====
        float xp1v = 0.f;
        if (l >= 4 && l < 8 && s >= 4)
            xp1v = sXp1[(((s - 4) & 3) << 5) + (gl << 3) + w];
        float pre = ((l & 4) ? dot1[gl] + bs1v + xp1v : dot0[gl] + xv);
        float kx  = (gl == 2) ? 2.f * pre : pre;        // tanh needs 2x
        float ev  = __expf(-kx);
        float rv  = __fdividef(1.f, 1.f + ev);
        float act = (gl == 2) ? fmaf(2.f, rv, -1.f) : rv;

        int base = l & 4;
        float iv = __shfl_sync(0xffffffffu, act, base + 0);
        float fv = __shfl_sync(0xffffffffu, act, base + 1);
        float gv = __shfl_sync(0xffffffffu, act, base + 2);
        float ov = __shfl_sync(0xffffffffu, act, base + 3);

        float h1n = 0.f;
        if (l == 0 && s < TT) {                   // layer 0: h0_s
            c0 = fmaf(fv, c0, iv * gv);
            sPub[w] = ov * fast_tanh(c0);
        }
        if (l == 4 && s >= 4) {                   // layer 1: h1_{s-4}
            c1 = fmaf(fv, c1, iv * gv);
            h1n = ov * fast_tanh(c1);
            sPub[8 + w] = h1n;
        }
        __syncthreads();

        // ===== publish (tid 0 only -> release covers its own stores) =====
        if (tid == 0) {
            float4 p0 = *(const float4*)&sPub[0];
            float4 p1 = *(const float4*)&sPub[4];
            float4 q0 = *(const float4*)&sPub[8];
            float4 q1 = *(const float4*)&sPub[12];
            float4* dst = (float4*)g_pubH[(s + 1) & 1];
            __stcg(dst + 2 * b,           p0);
            __stcg(dst + 2 * b + 1,       p1);
            __stcg(dst + 256 + 2 * b,     q0);
            __stcg(dst + 256 + 2 * b + 1, q1);
            if (s < TT) {                 // h0 history, PRE-release (ordered)
                float4* hd = (float4*)&g_h0hist[(size_t)s * HDIM + (b << 3)];
                __stcg(hd,     p0);
                __stcg(hd + 1, p1);
            }
            asm volatile("st.release.gpu.global.u32 [%0], %1;"
                         :: "l"(&g_flag[b]), "r"((unsigned)(s + 1)) : "memory");
        }

        // ===== h1 history (off the release path, lane 4) =====
        if (l == 4 && s >= 4) {
            __stcg(&g_h1[(size_t)(s - 4) * HDIM + e], h1n);
        }

        xv = nxv;
    }
}

// ---------------- FC + log_softmax ----------------
__global__ __launch_bounds__(128) void fc_logsoftmax_kernel(
    const float* __restrict__ fcw,    // [109][1024]
    const float* __restrict__ fcb,    // [109]
    float* __restrict__ out)          // [T][109]
{
    __shared__ float sH[8 * 1024];
    __shared__ float sL[8][112];
    __shared__ float sLse[8];
    int t0 = blockIdx.x * 8;
    int tid = threadIdx.x;

    const float4* hg = (const float4*)(g_h1 + (size_t)t0 * HDIM);
    float4* sH4 = (float4*)sH;
#pragma unroll
    for (int q = 0; q < 16; q++) sH4[tid + 128 * q] = __ldg(hg + tid + 128 * q);
    __syncthreads();

    if (tid < INDIM) {
        float acc[8];
#pragma unroll
        for (int i = 0; i < 8; i++) acc[i] = 0.f;
        const float4* w4 = (const float4*)(fcw + (size_t)tid * HDIM);
        for (int k4 = 0; k4 < 256; k4++) {
            float4 w = __ldg(w4 + k4);
#pragma unroll
            for (int tt = 0; tt < 8; tt++) {
                float4 hv = sH4[tt * 256 + k4];
                acc[tt] = fmaf(w.x, hv.x,
                          fmaf(w.y, hv.y,
                          fmaf(w.z, hv.z,
                          fmaf(w.w, hv.w, acc[tt]))));
            }
        }
        float bb = __ldg(&fcb[tid]);
#pragma unroll
        for (int tt = 0; tt < 8; tt++) sL[tt][tid] = acc[tt] + bb;
    }
    __syncthreads();

    if (tid < 8) {
        float m = -1e30f;
        for (int n = 0; n < INDIM; n++) m = fmaxf(m, sL[tid][n]);
        float s = 0.f;
        for (int n = 0; n < INDIM; n++) s += expf(sL[tid][n] - m);
        sLse[tid] = m + logf(s);
    }
    __syncthreads();

    for (int idx = tid; idx < 8 * INDIM; idx += 128) {
        int tt = idx / INDIM, n = idx - tt * INDIM;
        out[(size_t)(t0 + tt) * INDIM + n] = sL[tt][n] - sLse[tt];
    }
}

// ---------------- launcher ----------------
extern "C" void kernel_launch(void* const* d_in, const int* in_sizes, int n_in,
                              void* d_out, int out_size) {
    const float* input = (const float*)d_in[0];
    const float* W_ih0 = (const float*)d_in[1];
    const float* W_hh0 = (const float*)d_in[2];
    const float* b_ih0 = (const float*)d_in[3];
    const float* b_hh0 = (const float*)d_in[4];
    const float* W_ih1 = (const float*)d_in[5];
    const float* W_hh1 = (const float*)d_in[6];
    const float* b_ih1 = (const float*)d_in[7];
    const float* b_hh1 = (const float*)d_in[8];
    const float* fc_w  = (const float*)d_in[9];
    const float* fc_b  = (const float*)d_in[10];
    float* out = (float*)d_out;

    cudaFuncSetAttribute(lstm_fused_kernel,
                         cudaFuncAttributeMaxDynamicSharedMemorySize, FUS_SMEM);

    // xp0 = input @ W_ih0^T + b_ih0 + b_hh0
    gemm_xproj_small<<<dim3(TT / 64, GDIM / 32), 256>>>(input, W_ih0, b_ih0, b_hh0);

    // fused 2-layer recurrence -> g_h1
    reset_state_kernel<<<1, 1024>>>();
    lstm_fused_kernel<<<NBLK, 256, FUS_SMEM>>>(W_hh0, W_ih1, W_hh1, b_ih1, b_hh1);

    // logits + log_softmax
    fc_logsoftmax_kernel<<<TT / 8, 128>>>(fc_w, fc_b, out);
}

// round 15
// speedup vs baseline: 1.7412x; 1.3442x over previous
#include <cuda_runtime.h>
#include <math.h>

// ---------------- problem dims ----------------
#define TT        8192
#define INDIM     109
#define HDIM      1024
#define GDIM      4096           // 4*HDIM
#define NBLK      128            // LSTM blocks: 128 * 8 elems = 1024
#define EPB       8              // h-elements per block

// ---------------- device scratch ----------------
__device__ float g_xp[TT * GDIM];                 // 128 MB: xp0 projections
__device__ float g_h1[TT * HDIM];                 // 32 MB layer-1 h history
// publish buffers: [parity][0..1023]=h0, [1024..2047]=h1 (float4-aligned)
__device__ __align__(16) float g_pubH[2][2048];
__device__ __align__(16) unsigned g_flag[NBLK];   // packed u32 flags (4 lines)

// ---------------- small helpers ----------------
__device__ __forceinline__ unsigned long long fma2(unsigned long long a,
                                                   unsigned long long b,
                                                   unsigned long long c) {
    unsigned long long d;
    asm("fma.rn.f32x2 %0, %1, %2, %3;" : "=l"(d) : "l"(a), "l"(b), "l"(c));
    return d;
}
__device__ __forceinline__ float2 unpack2(unsigned long long v) {
    float2 f;
    asm("mov.b64 {%0,%1}, %2;" : "=f"(f.x), "=f"(f.y) : "l"(v));
    return f;
}
__device__ __forceinline__ float fast_tanh(float x) {
    float e = __expf(-2.f * x);
    return fmaf(2.f, __fdividef(1.f, 1.f + e), -1.f);
}

__global__ void reset_state_kernel() {
    int i = threadIdx.x;                  // 1024 threads
    float* p = &g_pubH[0][0];             // 4096 floats total
#pragma unroll
    for (int q = 0; q < 4; q++) p[i + 1024 * q] = 0.f;
    if (i < NBLK) g_flag[i] = 0u;
}

// ---------------- xp0: [T,109] @ [4096,109]^T + bias ----------------
__global__ __launch_bounds__(256) void gemm_xproj_small(
    const float* __restrict__ A,      // [T][109]
    const float* __restrict__ B,      // [4096][109]
    const float* __restrict__ bias1,
    const float* __restrict__ bias2)
{
    __shared__ float sA[64][113];
    __shared__ float sB[32][113];
    int t0 = blockIdx.x * 64;
    int r0 = blockIdx.y * 32;
    int tid = threadIdx.x;
    int tx = tid & 15;
    int ty = tid >> 4;

    for (int idx = tid; idx < 64 * INDIM; idx += 256) {
        int row = idx / INDIM, k = idx - row * INDIM;
        sA[row][k] = A[(size_t)(t0 + row) * INDIM + k];
    }
    for (int idx = tid; idx < 32 * INDIM; idx += 256) {
        int row = idx / INDIM, k = idx - row * INDIM;
        sB[row][k] = B[(size_t)(r0 + row) * INDIM + k];
    }
    __syncthreads();

    float acc[4][2];
#pragma unroll
    for (int i = 0; i < 4; i++)
#pragma unroll
        for (int j = 0; j < 2; j++) acc[i][j] = 0.f;

    for (int k = 0; k < INDIM; k++) {
        float a[4], b[2];
#pragma unroll
        for (int i = 0; i < 4; i++) a[i] = sA[ty * 4 + i][k];
#pragma unroll
        for (int j = 0; j < 2; j++) b[j] = sB[tx * 2 + j][k];
#pragma unroll
        for (int i = 0; i < 4; i++)
#pragma unroll
            for (int j = 0; j < 2; j++) acc[i][j] = fmaf(a[i], b[j], acc[i][j]);
    }

#pragma unroll
    for (int j = 0; j < 2; j++) {
        int r = r0 + tx * 2 + j;
        float bs = __ldg(&bias1[r]) + __ldg(&bias2[r]);
#pragma unroll
        for (int i = 0; i < 4; i++) {
            int t = t0 + ty * 4 + i;
            g_xp[(size_t)t * GDIM + r] = acc[i][j] + bs;
        }
    }
}

// ---------------- fused 2-layer LSTM (R12 + merged 8-value reduce) --------
// 128 blocks x 256 threads. Block b owns h0/h1 elems [8b, 8b+8).
// Warp w owns element e = 8b+w of both layers.
// Step s computes h0_s (layer 0) and h1_{s-2} (layer 1):
//   pre-poll  : a1 = W_ih1 @ h0_{s-2}   (staged at step s-1)
//   poll      : R5 barrier — warp 0, one ld.acquire.v4 per lane, 4 lines
//   stage     : h0_{s-1}, h1_{s-3} -> SMEM (ldcg, parity s&1)
//   post-poll : a0 = W_hh0(RF) @ h0_{s-1}; a1 += W_hh1(SMEM+RF) @ h1_{s-3};
//               MERGED REDUCE: 8 values over 32 lanes in 10 shuffles
//               (bit-trading butterfly) instead of 8x5=40; lane j ends with
//               pre_j; parallel activations on lanes 0-7; quad shfl; c0 on
//               lane 0, c1 on lane 4; publish; release.
// SMEM: sWih1 131072 | sWhh1 81920 | sH0 4096 | sH1 4096 | sPub 64
#define FUS_SMEM (131072 + 81920 + 4096 + 4096 + 64)

__global__ __launch_bounds__(256, 1) void lstm_fused_kernel(
    const float* __restrict__ Whh0,   // [4096][1024]
    const float* __restrict__ Wih1,   // [4096][1024]
    const float* __restrict__ Whh1,   // [4096][1024]
    const float* __restrict__ b_ih1,
    const float* __restrict__ b_hh1)
{
    extern __shared__ char smem[];
    float4* sWih1 = (float4*)(smem);                            // 32 rows x 256 f4
    float4* sWhh1 = (float4*)(smem + 131072);                   // 32 rows x 160 f4
    float4* sH0   = (float4*)(smem + 131072 + 81920);           // 256 f4
    float4* sH1   = (float4*)(smem + 131072 + 81920 + 4096);    // 256 f4
    float*  sPub  = (float*)(smem + 131072 + 81920 + 8192);     // 16 floats

    int b   = blockIdx.x;
    int tid = threadIdx.x;
    int w   = tid >> 5;
    int l   = tid & 31;
    int e   = (b << 3) + w;
    int gl  = l & 3;                  // gate index for lanes 0..7

    // ---- RF weights ----
    ulonglong2 W0[4][8];              // W_hh0, full rows
    ulonglong2 W1r[4][3];             // W_hh1, k=5..7 (cols 640..1023)
#pragma unroll
    for (int g = 0; g < 4; g++) {
        const ulonglong2* r0p =
            (const ulonglong2*)(Whh0 + (size_t)((g << 10) + e) * HDIM);
        const ulonglong2* r1p =
            (const ulonglong2*)(Whh1 + (size_t)((g << 10) + e) * HDIM);
#pragma unroll
        for (int k = 0; k < 8; k++) W0[g][k] = r0p[l + 32 * k];
#pragma unroll
        for (int k = 0; k < 3; k++) W1r[g][k] = r1p[l + 32 * (5 + k)];
    }

    // ---- SMEM weights (cooperative) ----
    for (int idx = tid; idx < 32 * 256; idx += 256) {
        int rl = idx >> 8, c4 = idx & 255;
        int g = rl >> 3, ww = rl & 7;
        sWih1[idx] = ((const float4*)(Wih1 +
            (size_t)((g << 10) + (b << 3) + ww) * HDIM))[c4];
    }
    for (int idx = tid; idx < 32 * 160; idx += 256) {
        int rl = idx / 160, c4 = idx - rl * 160;
        int g = rl >> 3, ww = rl & 7;
        sWhh1[idx] = ((const float4*)(Whh1 +
            (size_t)((g << 10) + (b << 3) + ww) * HDIM))[c4];
    }

    // layer-1 bias sum on lanes 4..7 (lane 4+g holds gate g's bias)
    float bs1v = 0.f;
    if (l >= 4 && l < 8) {
        int r = (gl << 10) + e;
        bs1v = __ldg(&b_ih1[r]) + __ldg(&b_hh1[r]);
    }

    // init SMEM h buffers + pub staging to zero
    sH0[tid] = make_float4(0.f, 0.f, 0.f, 0.f);
    sH1[tid] = make_float4(0.f, 0.f, 0.f, 0.f);
    if (tid < 16) sPub[tid] = 0.f;
    float c0 = 0.f, c1 = 0.f;         // c0 on lane 0, c1 on lane 4
    __syncthreads();

    const uint4* flags4 = (const uint4*)g_flag;

    // prefetch xp0 for s=0: lane g in 0..3 loads gate g
    float xv = 0.f;
    if (l < 4) xv = __ldg(g_xp + (gl << 10) + e);

    const ulonglong2* H0 = (const ulonglong2*)sH0;
    const ulonglong2* H1 = (const ulonglong2*)sH1;
    const ulonglong2* wi = (const ulonglong2*)sWih1;
    const ulonglong2* wh = (const ulonglong2*)sWhh1;

    for (int s = 0; s <= TT + 1; s++) {
        // ===== pre-poll: W_ih1 @ h0_{s-2} (staged at step s-1) =====
        unsigned long long a1[4][2];
#pragma unroll
        for (int g = 0; g < 4; g++) { a1[g][0] = 0ull; a1[g][1] = 0ull; }
#pragma unroll
        for (int k = 0; k < 8; k++) {
            ulonglong2 hv = H0[32 * k + l];
#pragma unroll
            for (int g = 0; g < 4; g++) {
                ulonglong2 wv = wi[(size_t)((g << 3) + w) * 256 + 32 * k + l];
                a1[g][0] = fma2(wv.x, hv.x, a1[g][0]);
                a1[g][1] = fma2(wv.y, hv.y, a1[g][1]);
            }
        }

        // prefetch xp0 for next step (consumed one step later)
        float nxv = 0.f;
        if (l < 4 && s + 1 < TT)
            nxv = __ldg(g_xp + (size_t)(s + 1) * GDIM + (gl << 10) + e);

        // ===== poll (R5 barrier, byte-for-byte) =====
        if (s) {
            if (w == 0) {
                unsigned need = (unsigned)s;
                bool ok;
                do {
                    uint4 v;
                    asm volatile(
                        "ld.acquire.gpu.global.v4.u32 {%0,%1,%2,%3}, [%4];"
                        : "=r"(v.x), "=r"(v.y), "=r"(v.z), "=r"(v.w)
                        : "l"(flags4 + l) : "memory");
                    ok = v.x >= need && v.y >= need && v.z >= need && v.w >= need;
                } while (!__all_sync(0xffffffffu, ok));
            }
        }
        __syncthreads();   // also separates pre-poll reads of sH0 from restage

        // ===== stage h0_{s-1}, h1_{s-3} =====
        {
            const float4* pub4 = (const float4*)g_pubH[s & 1];
            sH0[tid] = __ldcg(pub4 + tid);
            sH1[tid] = __ldcg(pub4 + 256 + tid);
        }
        __syncthreads();

        // ===== post-poll: W_hh0 @ h0_{s-1}  and  a1 += W_hh1 @ h1_{s-3} =====
        unsigned long long a0[4][2];
#pragma unroll
        for (int g = 0; g < 4; g++) { a0[g][0] = 0ull; a0[g][1] = 0ull; }
#pragma unroll
        for (int k = 0; k < 8; k++) {
            ulonglong2 h0v = H0[32 * k + l];
            ulonglong2 h1v = H1[32 * k + l];
#pragma unroll
            for (int g = 0; g < 4; g++) {
                a0[g][0] = fma2(W0[g][k].x, h0v.x, a0[g][0]);
                a0[g][1] = fma2(W0[g][k].y, h0v.y, a0[g][1]);
                ulonglong2 wv1 = (k < 5)
                    ? wh[(size_t)((g << 3) + w) * 160 + 32 * k + l]
                    : W1r[g][k - 5];
                a1[g][0] = fma2(wv1.x, h1v.x, a1[g][0]);
                a1[g][1] = fma2(wv1.y, h1v.y, a1[g][1]);
            }
        }

        // ===== merged 8-value reduce (bit-trading butterfly, 10 shfl) =====
        // v[0..3] = layer-0 gates, v[4..7] = layer-1 gates.
        float v[8];
#pragma unroll
        for (int g = 0; g < 4; g++) {
            float2 lo0 = unpack2(a0[g][0]);
            float2 hi0 = unpack2(a0[g][1]);
            v[g] = (lo0.x + lo0.y) + (hi0.x + hi0.y);
            float2 lo1 = unpack2(a1[g][0]);
            float2 hi1 = unpack2(a1[g][1]);
            v[4 + g] = (lo1.x + lo1.y) + (hi1.x + hi1.y);
        }
        bool hi4 = (l & 16) != 0;
        float m[4];
#pragma unroll
        for (int i = 0; i < 4; i++) {
            float a = hi4 ? v[i + 4] : v[i];
            float bb = hi4 ? v[i] : v[i + 4];
            m[i] = a + __shfl_xor_sync(0xffffffffu, bb, 16);
        }
        bool hi3 = (l & 8) != 0;
        float x2[2];
#pragma unroll
        for (int i = 0; i < 2; i++) {
            float a = hi3 ? m[i + 2] : m[i];
            float bb = hi3 ? m[i] : m[i + 2];
            x2[i] = a + __shfl_xor_sync(0xffffffffu, bb, 8);
        }
        bool hi2 = (l & 4) != 0;
        {
            float a = hi2 ? x2[1] : x2[0];
            float bb = hi2 ? x2[0] : x2[1];
            x2[0] = a + __shfl_xor_sync(0xffffffffu, bb, 4);
        }
        float y = x2[0];
        y += __shfl_xor_sync(0xffffffffu, y, 2);
        y += __shfl_xor_sync(0xffffffffu, y, 1);
        // value j now complete on lanes with (bit4,bit3,bit2)=(j2,j1,j0),
        // i.e. lanes 4*j (+0..3). Gather: lane j needs value j -> src 4*(l&7).
        float pre_raw = __shfl_sync(0xffffffffu, y, (l & 7) << 2);

        // ===== parallel gate activations (lanes 0..7, branch-free) =====
        float pre = pre_raw + ((l & 4) ? bs1v : xv);
        float kx  = (gl == 2) ? 2.f * pre : pre;        // tanh needs 2x
        float ev  = __expf(-kx);
        float rv  = __fdividef(1.f, 1.f + ev);
        float act = (gl == 2) ? fmaf(2.f, rv, -1.f) : rv;

        int base = l & 4;
        float iv = __shfl_sync(0xffffffffu, act, base + 0);
        float fv = __shfl_sync(0xffffffffu, act, base + 1);
        float gv = __shfl_sync(0xffffffffu, act, base + 2);
        float ov = __shfl_sync(0xffffffffu, act, base + 3);

        float h1n = 0.f;
        if (l == 0 && s < TT) {                   // layer 0: h0_s
            c0 = fmaf(fv, c0, iv * gv);
            sPub[w] = ov * fast_tanh(c0);
        }
        if (l == 4 && s >= 2) {                   // layer 1: h1_{s-2}
            c1 = fmaf(fv, c1, iv * gv);
            h1n = ov * fast_tanh(c1);
            sPub[8 + w] = h1n;
        }
        __syncthreads();

        // ===== publish (tid 0 only -> release covers its own stores) =====
        if (tid == 0) {
            float4 p0 = *(const float4*)&sPub[0];
            float4 p1 = *(const float4*)&sPub[4];
            float4 q0 = *(const float4*)&sPub[8];
            float4 q1 = *(const float4*)&sPub[12];
            float4* dst = (float4*)g_pubH[(s + 1) & 1];
            __stcg(dst + 2 * b,           p0);
            __stcg(dst + 2 * b + 1,       p1);
            __stcg(dst + 256 + 2 * b,     q0);
            __stcg(dst + 256 + 2 * b + 1, q1);
            asm volatile("st.release.gpu.global.u32 [%0], %1;"
                         :: "l"(&g_flag[b]), "r"((unsigned)(s + 1)) : "memory");
        }

        // ===== h1 history (off the release path, lane 4) =====
        if (l == 4 && s >= 2) {
            __stcg(&g_h1[(size_t)(s - 2) * HDIM + e], h1n);
        }

        xv = nxv;
    }
}

// ---------------- FC + log_softmax ----------------
__global__ __launch_bounds__(128) void fc_logsoftmax_kernel(
    const float* __restrict__ fcw,    // [109][1024]
    const float* __restrict__ fcb,    // [109]
    float* __restrict__ out)          // [T][109]
{
    __shared__ float sH[8 * 1024];
    __shared__ float sL[8][112];
    __shared__ float sLse[8];
    int t0 = blockIdx.x * 8;
    int tid = threadIdx.x;

    const float4* hg = (const float4*)(g_h1 + (size_t)t0 * HDIM);
    float4* sH4 = (float4*)sH;
#pragma unroll
    for (int q = 0; q < 16; q++) sH4[tid + 128 * q] = __ldg(hg + tid + 128 * q);
    __syncthreads();

    if (tid < INDIM) {
        float acc[8];
#pragma unroll
        for (int i = 0; i < 8; i++) acc[i] = 0.f;
        const float4* w4 = (const float4*)(fcw + (size_t)tid * HDIM);
        for (int k4 = 0; k4 < 256; k4++) {
            float4 w = __ldg(w4 + k4);
#pragma unroll
            for (int tt = 0; tt < 8; tt++) {
                float4 hv = sH4[tt * 256 + k4];
                acc[tt] = fmaf(w.x, hv.x,
                          fmaf(w.y, hv.y,
                          fmaf(w.z, hv.z,
                          fmaf(w.w, hv.w, acc[tt]))));
            }
        }
        float bb = __ldg(&fcb[tid]);
#pragma unroll
        for (int tt = 0; tt < 8; tt++) sL[tt][tid] = acc[tt] + bb;
    }
    __syncthreads();

    if (tid < 8) {
        float m = -1e30f;
        for (int n = 0; n < INDIM; n++) m = fmaxf(m, sL[tid][n]);
        float s = 0.f;
        for (int n = 0; n < INDIM; n++) s += expf(sL[tid][n] - m);
        sLse[tid] = m + logf(s);
    }
    __syncthreads();

    for (int idx = tid; idx < 8 * INDIM; idx += 128) {
        int tt = idx / INDIM, n = idx - tt * INDIM;
        out[(size_t)(t0 + tt) * INDIM + n] = sL[tt][n] - sLse[tt];
    }
}

// ---------------- launcher ----------------
extern "C" void kernel_launch(void* const* d_in, const int* in_sizes, int n_in,
                              void* d_out, int out_size) {
    const float* input = (const float*)d_in[0];
    const float* W_ih0 = (const float*)d_in[1];
    const float* W_hh0 = (const float*)d_in[2];
    const float* b_ih0 = (const float*)d_in[3];
    const float* b_hh0 = (const float*)d_in[4];
    const float* W_ih1 = (const float*)d_in[5];
    const float* W_hh1 = (const float*)d_in[6];
    const float* b_ih1 = (const float*)d_in[7];
    const float* b_hh1 = (const float*)d_in[8];
    const float* fc_w  = (const float*)d_in[9];
    const float* fc_b  = (const float*)d_in[10];
    float* out = (float*)d_out;

    cudaFuncSetAttribute(lstm_fused_kernel,
                         cudaFuncAttributeMaxDynamicSharedMemorySize, FUS_SMEM);

    // xp0 = input @ W_ih0^T + b_ih0 + b_hh0
    gemm_xproj_small<<<dim3(TT / 64, GDIM / 32), 256>>>(input, W_ih0, b_ih0, b_hh0);

    // fused 2-layer recurrence -> g_h1
    reset_state_kernel<<<1, 1024>>>();
    lstm_fused_kernel<<<NBLK, 256, FUS_SMEM>>>(W_hh0, W_ih1, W_hh1, b_ih1, b_hh1);

    // logits + log_softmax
    fc_logsoftmax_kernel<<<TT / 8, 128>>>(fc_w, fc_b, out);
}

// round 16
// speedup vs baseline: 1.7709x; 1.0171x over previous
#include <cuda_runtime.h>
#include <math.h>

// ---------------- problem dims ----------------
#define TT        8192
#define INDIM     109
#define HDIM      1024
#define GDIM      4096           // 4*HDIM
#define NBLK      128            // LSTM blocks: 128 * 8 elems = 1024
#define EPB       8              // h-elements per block

// ---------------- device scratch ----------------
__device__ float g_xp[TT * GDIM];                 // 128 MB: xp0 projections
__device__ float g_h1[TT * HDIM];                 // 32 MB layer-1 h history
// publish buffers: [parity][0..1023]=h0, [1024..2047]=h1 (float4-aligned)
__device__ __align__(16) float g_pubH[2][2048];
__device__ __align__(16) unsigned g_flag[NBLK];   // packed u32 flags (4 lines)

// ---------------- small helpers ----------------
__device__ __forceinline__ float fast_tanh(float x) {
    float e = __expf(-2.f * x);
    return fmaf(2.f, __fdividef(1.f, 1.f + e), -1.f);
}
__device__ __forceinline__ float dot4(float4 wv, float4 hv, float a) {
    a = fmaf(wv.x, hv.x, a);
    a = fmaf(wv.y, hv.y, a);
    a = fmaf(wv.z, hv.z, a);
    a = fmaf(wv.w, hv.w, a);
    return a;
}

__global__ void reset_state_kernel() {
    int i = threadIdx.x;                  // 1024 threads
    float* p = &g_pubH[0][0];             // 4096 floats total
#pragma unroll
    for (int q = 0; q < 4; q++) p[i + 1024 * q] = 0.f;
    if (i < NBLK) g_flag[i] = 0u;
}

// ---------------- xp0: [T,109] @ [4096,109]^T + bias ----------------
__global__ __launch_bounds__(256) void gemm_xproj_small(
    const float* __restrict__ A,      // [T][109]
    const float* __restrict__ B,      // [4096][109]
    const float* __restrict__ bias1,
    const float* __restrict__ bias2)
{
    __shared__ float sA[64][113];
    __shared__ float sB[32][113];
    int t0 = blockIdx.x * 64;
    int r0 = blockIdx.y * 32;
    int tid = threadIdx.x;
    int tx = tid & 15;
    int ty = tid >> 4;

    for (int idx = tid; idx < 64 * INDIM; idx += 256) {
        int row = idx / INDIM, k = idx - row * INDIM;
        sA[row][k] = A[(size_t)(t0 + row) * INDIM + k];
    }
    for (int idx = tid; idx < 32 * INDIM; idx += 256) {
        int row = idx / INDIM, k = idx - row * INDIM;
        sB[row][k] = B[(size_t)(r0 + row) * INDIM + k];
    }
    __syncthreads();

    float acc[4][2];
#pragma unroll
    for (int i = 0; i < 4; i++)
#pragma unroll
        for (int j = 0; j < 2; j++) acc[i][j] = 0.f;

    for (int k = 0; k < INDIM; k++) {
        float a[4], b[2];
#pragma unroll
        for (int i = 0; i < 4; i++) a[i] = sA[ty * 4 + i][k];
#pragma unroll
        for (int j = 0; j < 2; j++) b[j] = sB[tx * 2 + j][k];
#pragma unroll
        for (int i = 0; i < 4; i++)
#pragma unroll
            for (int j = 0; j < 2; j++) acc[i][j] = fmaf(a[i], b[j], acc[i][j]);
    }

#pragma unroll
    for (int j = 0; j < 2; j++) {
        int r = r0 + tx * 2 + j;
        float bs = __ldg(&bias1[r]) + __ldg(&bias2[r]);
#pragma unroll
        for (int i = 0; i < 4; i++) {
            int t = t0 + ty * 4 + i;
            g_xp[(size_t)t * GDIM + r] = acc[i][j] + bs;
        }
    }
}

// ---------------- fused 2-layer LSTM (hybrid slice x gate matvec) ---------
// 128 blocks x 256 threads. Block b owns h0/h1 elems [8b, 8b+8).
// MATVEC mapping: warp w -> (slice sl = w>>2, gate gm = w&3); slice covers
// 512 cols. Thread (w,l) owns rows {gate gm, elems j=0..7} x cols
// {sl*512 + 16-col quads l+32q, q=0..3}. Each warp reads only its 2KB
// h-slice per operand (h traffic 96KB -> 48KB/step vs row mapping).
// GATE mapping (unchanged from R15): warp w computes elem e=8b+w gates on
// lanes 0..7, c0 on lane 0, c1 on lane 4, publish via sPub.
// Step s computes h0_s (layer 0) and h1_{s-2} (layer 1):
//   pre-poll  : acc1[8] partial = W_ih1(slice) @ h0_{s-2}
//   poll      : R5 barrier — warp 0, one ld.acquire.v4 per lane, 4 lines
//   stage     : h0_{s-1}, h1_{s-3} -> SMEM (ldcg, parity s&1)
//   post-poll : acc0 = W_hh0(RF) @ h0_{s-1}; acc1 += W_hh1(SMEM+RF) @ h1_{s-3};
//               16-value bit-trading butterfly (16 shfl) -> lane l holds
//               partial value l>>1; STS sRed[w][16]; bar; gate lanes combine
//               the two slice partials (2 LDS + add); activations; publish.
// SMEM: sWih1 131072 | sWhh1 81920 | sH0 4096 | sH1 4096 | sPub 64 | sRed 512
#define FUS_SMEM (131072 + 81920 + 4096 + 4096 + 64 + 512)

__global__ __launch_bounds__(256, 1) void lstm_fused_kernel(
    const float* __restrict__ Whh0,   // [4096][1024]
    const float* __restrict__ Wih1,   // [4096][1024]
    const float* __restrict__ Whh1,   // [4096][1024]
    const float* __restrict__ b_ih1,
    const float* __restrict__ b_hh1)
{
    extern __shared__ char smem[];
    float4* sWih1 = (float4*)(smem);                            // 32 rows x 256 f4
    float4* sWhh1 = (float4*)(smem + 131072);                   // 20 rows x 256 f4
    float4* sH0   = (float4*)(smem + 131072 + 81920);           // 256 f4
    float4* sH1   = (float4*)(smem + 131072 + 81920 + 4096);    // 256 f4
    float*  sPub  = (float*)(smem + 131072 + 81920 + 8192);     // 16 floats
    float*  sRed  = (float*)(smem + 131072 + 81920 + 8192 + 64);// [8][16] floats

    int b   = blockIdx.x;
    int tid = threadIdx.x;
    int w   = tid >> 5;
    int l   = tid & 31;
    int e   = (b << 3) + w;           // elem for GATE phase
    int gl  = l & 3;                  // gate index for lanes 0..7
    int gm  = w & 3;                  // matvec gate for this warp
    int sl  = w >> 2;                 // matvec column slice (0 or 1)
    int qb  = sl * 128 + l;           // base quad index for this thread

    // ---- RF weights (hybrid mapping) ----
    float4 W0[8][4];                  // W_hh0: rows (gm, j=0..7), quads qb+32q
    float4 W1r[3][4];                 // W_hh1: rows (gm, j=5..7)
#pragma unroll
    for (int j = 0; j < 8; j++) {
        const float4* rp =
            (const float4*)(Whh0 + (size_t)((gm << 10) + (b << 3) + j) * HDIM);
#pragma unroll
        for (int q = 0; q < 4; q++) W0[j][q] = rp[qb + 32 * q];
    }
#pragma unroll
    for (int j = 0; j < 3; j++) {
        const float4* rp =
            (const float4*)(Whh1 + (size_t)((gm << 10) + (b << 3) + 5 + j) * HDIM);
#pragma unroll
        for (int q = 0; q < 4; q++) W1r[j][q] = rp[qb + 32 * q];
    }

    // ---- SMEM weights (cooperative) ----
    // wi: [32 rows][256 quads], row r = g*8 + j
    for (int idx = tid; idx < 32 * 256; idx += 256) {
        int rl = idx >> 8, c4 = idx & 255;
        int g = rl >> 3, ww = rl & 7;
        sWih1[idx] = ((const float4*)(Wih1 +
            (size_t)((g << 10) + (b << 3) + ww) * HDIM))[c4];
    }
    // wh1: [20 rows][256 quads], row rr = g*5 + j (j<5)
    for (int idx = tid; idx < 20 * 256; idx += 256) {
        int rr = idx >> 8, c4 = idx & 255;
        int g = rr / 5, j = rr - g * 5;
        sWhh1[idx] = ((const float4*)(Whh1 +
            (size_t)((g << 10) + (b << 3) + j) * HDIM))[c4];
    }

    // layer-1 bias sum on lanes 4..7 (lane 4+g holds gate g's bias for elem e)
    float bs1v = 0.f;
    if (l >= 4 && l < 8) {
        int r = (gl << 10) + e;
        bs1v = __ldg(&b_ih1[r]) + __ldg(&b_hh1[r]);
    }

    // init SMEM h buffers + staging to zero
    sH0[tid] = make_float4(0.f, 0.f, 0.f, 0.f);
    sH1[tid] = make_float4(0.f, 0.f, 0.f, 0.f);
    if (tid < 16) sPub[tid] = 0.f;
    if (tid < 128) sRed[tid] = 0.f;
    float c0 = 0.f, c1 = 0.f;         // c0 on lane 0, c1 on lane 4
    __syncthreads();

    const uint4* flags4 = (const uint4*)g_flag;

    // prefetch xp0 for s=0: lane g in 0..3 loads gate g of elem e
    float xv = 0.f;
    if (l < 4) xv = __ldg(g_xp + (gl << 10) + e);

    for (int s = 0; s <= TT + 1; s++) {
        // ===== pre-poll: acc1 partial = W_ih1(slice) @ h0_{s-2} =====
        float4 hv[4];
#pragma unroll
        for (int q = 0; q < 4; q++) hv[q] = sH0[qb + 32 * q];
        float acc1[8];
#pragma unroll
        for (int j = 0; j < 8; j++) {
            const float4* wr = sWih1 + (size_t)((gm << 3) + j) * 256;
            float a = 0.f;
#pragma unroll
            for (int q = 0; q < 4; q++) a = dot4(wr[qb + 32 * q], hv[q], a);
            acc1[j] = a;
        }

        // prefetch xp0 for next step (consumed one step later)
        float nxv = 0.f;
        if (l < 4 && s + 1 < TT)
            nxv = __ldg(g_xp + (size_t)(s + 1) * GDIM + (gl << 10) + e);

        // ===== poll (R5 barrier, byte-for-byte) =====
        if (s) {
            if (w == 0) {
                unsigned need = (unsigned)s;
                bool ok;
                do {
                    uint4 v;
                    asm volatile(
                        "ld.acquire.gpu.global.v4.u32 {%0,%1,%2,%3}, [%4];"
                        : "=r"(v.x), "=r"(v.y), "=r"(v.z), "=r"(v.w)
                        : "l"(flags4 + l) : "memory");
                    ok = v.x >= need && v.y >= need && v.z >= need && v.w >= need;
                } while (!__all_sync(0xffffffffu, ok));
            }
        }
        __syncthreads();   // also separates pre-poll reads of sH0 from restage

        // ===== stage h0_{s-1}, h1_{s-3} =====
        {
            const float4* pub4 = (const float4*)g_pubH[s & 1];
            sH0[tid] = __ldcg(pub4 + tid);
            sH1[tid] = __ldcg(pub4 + 256 + tid);
        }
        __syncthreads();

        // ===== post-poll: acc0 = W_hh0 @ h0_{s-1}; acc1 += W_hh1 @ h1_{s-3} =====
        float4 h0q[4], h1q[4];
#pragma unroll
        for (int q = 0; q < 4; q++) {
            h0q[q] = sH0[qb + 32 * q];
            h1q[q] = sH1[qb + 32 * q];
        }
        float acc0[8];
#pragma unroll
        for (int j = 0; j < 8; j++) {
            float a = 0.f;
#pragma unroll
            for (int q = 0; q < 4; q++) a = dot4(W0[j][q], h0q[q], a);
            acc0[j] = a;
        }
#pragma unroll
        for (int j = 0; j < 5; j++) {
            const float4* wr = sWhh1 + (size_t)(gm * 5 + j) * 256;
            float a = acc1[j];
#pragma unroll
            for (int q = 0; q < 4; q++) a = dot4(wr[qb + 32 * q], h1q[q], a);
            acc1[j] = a;
        }
#pragma unroll
        for (int j = 5; j < 8; j++) {
            float a = acc1[j];
#pragma unroll
            for (int q = 0; q < 4; q++) a = dot4(W1r[j - 5][q], h1q[q], a);
            acc1[j] = a;
        }

        // ===== 16-value bit-trading butterfly (16 shfl) =====
        // value index: v[j] = acc0[j] (layer0), v[8+j] = acc1[j] (layer1).
        float v8[8];
        {
            bool b4 = (l & 16) != 0;
#pragma unroll
            for (int i = 0; i < 8; i++) {
                float a = b4 ? acc1[i] : acc0[i];
                float o = b4 ? acc0[i] : acc1[i];
                v8[i] = a + __shfl_xor_sync(0xffffffffu, o, 16);
            }
        }
        float v4[4];
        {
            bool b3 = (l & 8) != 0;
#pragma unroll
            for (int i = 0; i < 4; i++) {
                float a = b3 ? v8[i + 4] : v8[i];
                float o = b3 ? v8[i] : v8[i + 4];
                v4[i] = a + __shfl_xor_sync(0xffffffffu, o, 8);
            }
        }
        float v2[2];
        {
            bool b2 = (l & 4) != 0;
#pragma unroll
            for (int i = 0; i < 2; i++) {
                float a = b2 ? v2[0] : 0.f;   // placeholder (rewritten below)
                (void)a;
                float x = b2 ? v4[i + 2] : v4[i];
                float o = b2 ? v4[i] : v4[i + 2];
                v2[i] = x + __shfl_xor_sync(0xffffffffu, o, 4);
            }
        }
        float y;
        {
            bool b1 = (l & 2) != 0;
            float x = b1 ? v2[1] : v2[0];
            float o = b1 ? v2[0] : v2[1];
            y = x + __shfl_xor_sync(0xffffffffu, o, 2);
            y += __shfl_xor_sync(0xffffffffu, y, 1);
        }
        // lane l holds complete slice-partial of value (l>>1):
        //   value = bit4*8 + bit3*4 + bit2*2 + bit1  (j = low 3 bits, layer = bit3... )
        if (!(l & 1)) sRed[(w << 4) + (l >> 1)] = y;
        __syncthreads();

        // ===== gate lanes combine slice partials + activations =====
        float pre_raw = 0.f;
        if (l < 8) {
            int L = l >> 2;               // 0 = layer0, 1 = layer1
            int v = (L << 3) + w;         // value index: layer*8 + elem j
            pre_raw = sRed[(gl << 4) + v] + sRed[((gl + 4) << 4) + v];
        }
        float pre = pre_raw + ((l & 4) ? bs1v : xv);
        float kx  = (gl == 2) ? 2.f * pre : pre;        // tanh needs 2x
        float ev  = __expf(-kx);
        float rv  = __fdividef(1.f, 1.f + ev);
        float act = (gl == 2) ? fmaf(2.f, rv, -1.f) : rv;

        int base = l & 4;
        float iv = __shfl_sync(0xffffffffu, act, base + 0);
        float fv = __shfl_sync(0xffffffffu, act, base + 1);
        float gv = __shfl_sync(0xffffffffu, act, base + 2);
        float ov = __shfl_sync(0xffffffffu, act, base + 3);

        float h1n = 0.f;
        if (l == 0 && s < TT) {                   // layer 0: h0_s
            c0 = fmaf(fv, c0, iv * gv);
            sPub[w] = ov * fast_tanh(c0);
        }
        if (l == 4 && s >= 2) {                   // layer 1: h1_{s-2}
            c1 = fmaf(fv, c1, iv * gv);
            h1n = ov * fast_tanh(c1);
            sPub[8 + w] = h1n;
        }
        __syncthreads();

        // ===== publish (tid 0 only -> release covers its own stores) =====
        if (tid == 0) {
            float4 p0 = *(const float4*)&sPub[0];
            float4 p1 = *(const float4*)&sPub[4];
            float4 q0 = *(const float4*)&sPub[8];
            float4 q1 = *(const float4*)&sPub[12];
            float4* dst = (float4*)g_pubH[(s + 1) & 1];
            __stcg(dst + 2 * b,           p0);
            __stcg(dst + 2 * b + 1,       p1);
            __stcg(dst + 256 + 2 * b,     q0);
            __stcg(dst + 256 + 2 * b + 1, q1);
            asm volatile("st.release.gpu.global.u32 [%0], %1;"
                         :: "l"(&g_flag[b]), "r"((unsigned)(s + 1)) : "memory");
        }

        // ===== h1 history (off the release path, lane 4) =====
        if (l == 4 && s >= 2) {
            __stcg(&g_h1[(size_t)(s - 2) * HDIM + e], h1n);
        }

        xv = nxv;
    }
}

// ---------------- FC + log_softmax ----------------
__global__ __launch_bounds__(128) void fc_logsoftmax_kernel(
    const float* __restrict__ fcw,    // [109][1024]
    const float* __restrict__ fcb,    // [109]
    float* __restrict__ out)          // [T][109]
{
    __shared__ float sH[8 * 1024];
    __shared__ float sL[8][112];
    __shared__ float sLse[8];
    int t0 = blockIdx.x * 8;
    int tid = threadIdx.x;

    const float4* hg = (const float4*)(g_h1 + (size_t)t0 * HDIM);
    float4* sH4 = (float4*)sH;
#pragma unroll
    for (int q = 0; q < 16; q++) sH4[tid + 128 * q] = __ldg(hg + tid + 128 * q);
    __syncthreads();

    if (tid < INDIM) {
        float acc[8];
#pragma unroll
        for (int i = 0; i < 8; i++) acc[i] = 0.f;
        const float4* w4 = (const float4*)(fcw + (size_t)tid * HDIM);
        for (int k4 = 0; k4 < 256; k4++) {
            float4 w = __ldg(w4 + k4);
#pragma unroll
            for (int tt = 0; tt < 8; tt++) {
                float4 hv = sH4[tt * 256 + k4];
                acc[tt] = fmaf(w.x, hv.x,
                          fmaf(w.y, hv.y,
                          fmaf(w.z, hv.z,
                          fmaf(w.w, hv.w, acc[tt]))));
            }
        }
        float bb = __ldg(&fcb[tid]);
#pragma unroll
        for (int tt = 0; tt < 8; tt++) sL[tt][tid] = acc[tt] + bb;
    }
    __syncthreads();

    if (tid < 8) {
        float m = -1e30f;
        for (int n = 0; n < INDIM; n++) m = fmaxf(m, sL[tid][n]);
        float s = 0.f;
        for (int n = 0; n < INDIM; n++) s += expf(sL[tid][n] - m);
        sLse[tid] = m + logf(s);
    }
    __syncthreads();

    for (int idx = tid; idx < 8 * INDIM; idx += 128) {
        int tt = idx / INDIM, n = idx - tt * INDIM;
        out[(size_t)(t0 + tt) * INDIM + n] = sL[tt][n] - sLse[tt];
    }
}

// ---------------- launcher ----------------
extern "C" void kernel_launch(void* const* d_in, const int* in_sizes, int n_in,
                              void* d_out, int out_size) {
    const float* input = (const float*)d_in[0];
    const float* W_ih0 = (const float*)d_in[1];
    const float* W_hh0 = (const float*)d_in[2];
    const float* b_ih0 = (const float*)d_in[3];
    const float* b_hh0 = (const float*)d_in[4];
    const float* W_ih1 = (const float*)d_in[5];
    const float* W_hh1 = (const float*)d_in[6];
    const float* b_ih1 = (const float*)d_in[7];
    const float* b_hh1 = (const float*)d_in[8];
    const float* fc_w  = (const float*)d_in[9];
    const float* fc_b  = (const float*)d_in[10];
    float* out = (float*)d_out;

    cudaFuncSetAttribute(lstm_fused_kernel,
                         cudaFuncAttributeMaxDynamicSharedMemorySize, FUS_SMEM);

    // xp0 = input @ W_ih0^T + b_ih0 + b_hh0
    gemm_xproj_small<<<dim3(TT / 64, GDIM / 32), 256>>>(input, W_ih0, b_ih0, b_hh0);

    // fused 2-layer recurrence -> g_h1
    reset_state_kernel<<<1, 1024>>>();
    lstm_fused_kernel<<<NBLK, 256, FUS_SMEM>>>(W_hh0, W_ih1, W_hh1, b_ih1, b_hh1);

    // logits + log_softmax
    fc_logsoftmax_kernel<<<TT / 8, 128>>>(fc_w, fc_b, out);
}

// round 17
// speedup vs baseline: 1.8717x; 1.0569x over previous
#include <cuda_runtime.h>
#include <math.h>

// ---------------- problem dims ----------------
#define TT        8192
#define INDIM     109
#define HDIM      1024
#define GDIM      4096           // 4*HDIM
#define NBLK      128            // LSTM blocks: 128 * 8 elems = 1024
#define EPB       8              // h-elements per block

// ---------------- device scratch ----------------
__device__ float g_xp[TT * GDIM];                 // 128 MB: xp0 projections
__device__ float g_h1[TT * HDIM];                 // 32 MB layer-1 h history
// publish buffers: [parity][0..1023]=h0, [1024..2047]=h1 (float4-aligned)
__device__ __align__(16) float g_pubH[2][2048];
__device__ __align__(16) unsigned g_flag[NBLK];   // packed u32 flags (4 lines)

// ---------------- small helpers ----------------
__device__ __forceinline__ unsigned long long fma2(unsigned long long a,
                                                   unsigned long long b,
                                                   unsigned long long c) {
    unsigned long long d;
    asm("fma.rn.f32x2 %0, %1, %2, %3;" : "=l"(d) : "l"(a), "l"(b), "l"(c));
    return d;
}
__device__ __forceinline__ float2 unpack2(unsigned long long v) {
    float2 f;
    asm("mov.b64 {%0,%1}, %2;" : "=f"(f.x), "=f"(f.y) : "l"(v));
    return f;
}
__device__ __forceinline__ float fast_tanh(float x) {
    float e = __expf(-2.f * x);
    return fmaf(2.f, __fdividef(1.f, 1.f + e), -1.f);
}

__global__ void reset_state_kernel() {
    int i = threadIdx.x;                  // 1024 threads
    float* p = &g_pubH[0][0];             // 4096 floats total
#pragma unroll
    for (int q = 0; q < 4; q++) p[i + 1024 * q] = 0.f;
    if (i < NBLK) g_flag[i] = 0u;
}

// ---------------- xp0: [T,109] @ [4096,109]^T + bias ----------------
__global__ __launch_bounds__(256) void gemm_xproj_small(
    const float* __restrict__ A,      // [T][109]
    const float* __restrict__ B,      // [4096][109]
    const float* __restrict__ bias1,
    const float* __restrict__ bias2)
{
    __shared__ float sA[64][113];
    __shared__ float sB[32][113];
    int t0 = blockIdx.x * 64;
    int r0 = blockIdx.y * 32;
    int tid = threadIdx.x;
    int tx = tid & 15;
    int ty = tid >> 4;

    for (int idx = tid; idx < 64 * INDIM; idx += 256) {
        int row = idx / INDIM, k = idx - row * INDIM;
        sA[row][k] = A[(size_t)(t0 + row) * INDIM + k];
    }
    for (int idx = tid; idx < 32 * INDIM; idx += 256) {
        int row = idx / INDIM, k = idx - row * INDIM;
        sB[row][k] = B[(size_t)(r0 + row) * INDIM + k];
    }
    __syncthreads();

    float acc[4][2];
#pragma unroll
    for (int i = 0; i < 4; i++)
#pragma unroll
        for (int j = 0; j < 2; j++) acc[i][j] = 0.f;

    for (int k = 0; k < INDIM; k++) {
        float a[4], b[2];
#pragma unroll
        for (int i = 0; i < 4; i++) a[i] = sA[ty * 4 + i][k];
#pragma unroll
        for (int j = 0; j < 2; j++) b[j] = sB[tx * 2 + j][k];
#pragma unroll
        for (int i = 0; i < 4; i++)
#pragma unroll
            for (int j = 0; j < 2; j++) acc[i][j] = fmaf(a[i], b[j], acc[i][j]);
    }

#pragma unroll
    for (int j = 0; j < 2; j++) {
        int r = r0 + tx * 2 + j;
        float bs = __ldg(&bias1[r]) + __ldg(&bias2[r]);
#pragma unroll
        for (int i = 0; i < 4; i++) {
            int t = t0 + ty * 4 + i;
            g_xp[(size_t)t * GDIM + r] = acc[i][j] + bs;
        }
    }
}

// ---------------- fused 2-layer LSTM (R16 partition + f32x2 math) ---------
// 128 blocks x 256 threads. Block b owns h0/h1 elems [8b, 8b+8).
// MATVEC mapping: warp w -> (slice sl = w>>2, gate gm = w&3); slice covers
// 512 cols. Thread (w,l) owns rows {gate gm, elems j=0..7} x cols
// {sl*512 + 16-col quads l+32q, q=0..3}. Each warp reads only its 2KB
// h-slice per operand. All matvec FMAs are packed fma.rn.f32x2 (halves
// FMA issue count vs R16: 384 FFMA -> 192 FFMA2 per thread per step).
// GATE mapping: warp w computes elem e=8b+w gates on lanes 0..7,
// c0 on lane 0, c1 on lane 4, publish via sPub.
// Step s computes h0_s (layer 0) and h1_{s-2} (layer 1):
//   pre-poll  : acc1[8] partial = W_ih1(slice) @ h0_{s-2}   (packed)
//   poll      : R5 barrier — warp 0, one ld.acquire.v4 per lane, 4 lines
//   stage     : h0_{s-1}, h1_{s-3} -> SMEM (ldcg, parity s&1)
//   post-poll : acc0 = W_hh0(RF) @ h0_{s-1}; acc1 += W_hh1(SMEM+RF) @ h1_{s-3}
//               (packed); 16-value bit-trading butterfly (16 shfl); STS
//               sRed[w][16]; bar; gate lanes combine slice partials;
//               activations; publish; release.
// SMEM: sWih1 131072 | sWhh1 81920 | sH0 4096 | sH1 4096 | sPub 64 | sRed 512
#define FUS_SMEM (131072 + 81920 + 4096 + 4096 + 64 + 512)

__global__ __launch_bounds__(256, 1) void lstm_fused_kernel(
    const float* __restrict__ Whh0,   // [4096][1024]
    const float* __restrict__ Wih1,   // [4096][1024]
    const float* __restrict__ Whh1,   // [4096][1024]
    const float* __restrict__ b_ih1,
    const float* __restrict__ b_hh1)
{
    extern __shared__ char smem[];
    float4* sWih1 = (float4*)(smem);                            // 32 rows x 256 f4
    float4* sWhh1 = (float4*)(smem + 131072);                   // 20 rows x 256 f4
    float4* sH0   = (float4*)(smem + 131072 + 81920);           // 256 f4
    float4* sH1   = (float4*)(smem + 131072 + 81920 + 4096);    // 256 f4
    float*  sPub  = (float*)(smem + 131072 + 81920 + 8192);     // 16 floats
    float*  sRed  = (float*)(smem + 131072 + 81920 + 8192 + 64);// [8][16] floats

    int b   = blockIdx.x;
    int tid = threadIdx.x;
    int w   = tid >> 5;
    int l   = tid & 31;
    int e   = (b << 3) + w;           // elem for GATE phase
    int gl  = l & 3;                  // gate index for lanes 0..7
    int gm  = w & 3;                  // matvec gate for this warp
    int sl  = w >> 2;                 // matvec column slice (0 or 1)
    int qb  = sl * 128 + l;           // base quad index for this thread

    // ---- RF weights (hybrid mapping, packed) ----
    ulonglong2 W0[8][4];              // W_hh0: rows (gm, j=0..7), quads qb+32q
    ulonglong2 W1r[3][4];             // W_hh1: rows (gm, j=5..7)
#pragma unroll
    for (int j = 0; j < 8; j++) {
        const ulonglong2* rp =
            (const ulonglong2*)(Whh0 + (size_t)((gm << 10) + (b << 3) + j) * HDIM);
#pragma unroll
        for (int q = 0; q < 4; q++) W0[j][q] = rp[qb + 32 * q];
    }
#pragma unroll
    for (int j = 0; j < 3; j++) {
        const ulonglong2* rp =
            (const ulonglong2*)(Whh1 + (size_t)((gm << 10) + (b << 3) + 5 + j) * HDIM);
#pragma unroll
        for (int q = 0; q < 4; q++) W1r[j][q] = rp[qb + 32 * q];
    }

    // ---- SMEM weights (cooperative) ----
    // wi: [32 rows][256 quads], row r = g*8 + j
    for (int idx = tid; idx < 32 * 256; idx += 256) {
        int rl = idx >> 8, c4 = idx & 255;
        int g = rl >> 3, ww = rl & 7;
        sWih1[idx] = ((const float4*)(Wih1 +
            (size_t)((g << 10) + (b << 3) + ww) * HDIM))[c4];
    }
    // wh1: [20 rows][256 quads], row rr = g*5 + j (j<5)
    for (int idx = tid; idx < 20 * 256; idx += 256) {
        int rr = idx >> 8, c4 = idx & 255;
        int g = rr / 5, j = rr - g * 5;
        sWhh1[idx] = ((const float4*)(Whh1 +
            (size_t)((g << 10) + (b << 3) + j) * HDIM))[c4];
    }

    // layer-1 bias sum on lanes 4..7 (lane 4+g holds gate g's bias for elem e)
    float bs1v = 0.f;
    if (l >= 4 && l < 8) {
        int r = (gl << 10) + e;
        bs1v = __ldg(&b_ih1[r]) + __ldg(&b_hh1[r]);
    }

    // init SMEM h buffers + staging to zero
    sH0[tid] = make_float4(0.f, 0.f, 0.f, 0.f);
    sH1[tid] = make_float4(0.f, 0.f, 0.f, 0.f);
    if (tid < 16) sPub[tid] = 0.f;
    if (tid < 128) sRed[tid] = 0.f;
    float c0 = 0.f, c1 = 0.f;         // c0 on lane 0, c1 on lane 4
    __syncthreads();

    const uint4* flags4 = (const uint4*)g_flag;

    // prefetch xp0 for s=0: lane g in 0..3 loads gate g of elem e
    float xv = 0.f;
    if (l < 4) xv = __ldg(g_xp + (gl << 10) + e);

    const ulonglong2* H0p = (const ulonglong2*)sH0;
    const ulonglong2* H1p = (const ulonglong2*)sH1;
    const ulonglong2* wip = (const ulonglong2*)sWih1;
    const ulonglong2* whp = (const ulonglong2*)sWhh1;

    for (int s = 0; s <= TT + 1; s++) {
        // ===== pre-poll: acc1 partial = W_ih1(slice) @ h0_{s-2} (packed) ====
        ulonglong2 hv[4];
#pragma unroll
        for (int q = 0; q < 4; q++) hv[q] = H0p[qb + 32 * q];
        float acc1[8];
#pragma unroll
        for (int j = 0; j < 8; j++) {
            const ulonglong2* wr = wip + (size_t)((gm << 3) + j) * 256;
            unsigned long long p = 0ull;
#pragma unroll
            for (int q = 0; q < 4; q++) {
                ulonglong2 wv = wr[qb + 32 * q];
                p = fma2(wv.x, hv[q].x, p);
                p = fma2(wv.y, hv[q].y, p);
            }
            float2 f = unpack2(p);
            acc1[j] = f.x + f.y;
        }

        // prefetch xp0 for next step (consumed one step later)
        float nxv = 0.f;
        if (l < 4 && s + 1 < TT)
            nxv = __ldg(g_xp + (size_t)(s + 1) * GDIM + (gl << 10) + e);

        // ===== poll (R5 barrier, byte-for-byte) =====
        if (s) {
            if (w == 0) {
                unsigned need = (unsigned)s;
                bool ok;
                do {
                    uint4 v;
                    asm volatile(
                        "ld.acquire.gpu.global.v4.u32 {%0,%1,%2,%3}, [%4];"
                        : "=r"(v.x), "=r"(v.y), "=r"(v.z), "=r"(v.w)
                        : "l"(flags4 + l) : "memory");
                    ok = v.x >= need && v.y >= need && v.z >= need && v.w >= need;
                } while (!__all_sync(0xffffffffu, ok));
            }
        }
        __syncthreads();   // also separates pre-poll reads of sH0 from restage

        // ===== stage h0_{s-1}, h1_{s-3} =====
        {
            const float4* pub4 = (const float4*)g_pubH[s & 1];
            sH0[tid] = __ldcg(pub4 + tid);
            sH1[tid] = __ldcg(pub4 + 256 + tid);
        }
        __syncthreads();

        // ===== post-poll (packed): acc0 = W_hh0 @ h0_{s-1};
        //                           acc1 += W_hh1 @ h1_{s-3} =====
        ulonglong2 h0q[4], h1q[4];
#pragma unroll
        for (int q = 0; q < 4; q++) {
            h0q[q] = H0p[qb + 32 * q];
            h1q[q] = H1p[qb + 32 * q];
        }
        float acc0[8];
#pragma unroll
        for (int j = 0; j < 8; j++) {
            unsigned long long p = 0ull;
#pragma unroll
            for (int q = 0; q < 4; q++) {
                p = fma2(W0[j][q].x, h0q[q].x, p);
                p = fma2(W0[j][q].y, h0q[q].y, p);
            }
            float2 f = unpack2(p);
            acc0[j] = f.x + f.y;
        }
#pragma unroll
        for (int j = 0; j < 5; j++) {
            const ulonglong2* wr = whp + (size_t)(gm * 5 + j) * 256;
            unsigned long long p = 0ull;
#pragma unroll
            for (int q = 0; q < 4; q++) {
                ulonglong2 wv = wr[qb + 32 * q];
                p = fma2(wv.x, h1q[q].x, p);
                p = fma2(wv.y, h1q[q].y, p);
            }
            float2 f = unpack2(p);
            acc1[j] += f.x + f.y;
        }
#pragma unroll
        for (int j = 5; j < 8; j++) {
            unsigned long long p = 0ull;
#pragma unroll
            for (int q = 0; q < 4; q++) {
                p = fma2(W1r[j - 5][q].x, h1q[q].x, p);
                p = fma2(W1r[j - 5][q].y, h1q[q].y, p);
            }
            float2 f = unpack2(p);
            acc1[j] += f.x + f.y;
        }

        // ===== 16-value bit-trading butterfly (16 shfl) =====
        float v8[8];
        {
            bool b4 = (l & 16) != 0;
#pragma unroll
            for (int i = 0; i < 8; i++) {
                float a = b4 ? acc1[i] : acc0[i];
                float o = b4 ? acc0[i] : acc1[i];
                v8[i] = a + __shfl_xor_sync(0xffffffffu, o, 16);
            }
        }
        float v4[4];
        {
            bool b3 = (l & 8) != 0;
#pragma unroll
            for (int i = 0; i < 4; i++) {
                float a = b3 ? v8[i + 4] : v8[i];
                float o = b3 ? v8[i] : v8[i + 4];
                v4[i] = a + __shfl_xor_sync(0xffffffffu, o, 8);
            }
        }
        float v2[2];
        {
            bool b2 = (l & 4) != 0;
#pragma unroll
            for (int i = 0; i < 2; i++) {
                float x = b2 ? v4[i + 2] : v4[i];
                float o = b2 ? v4[i] : v4[i + 2];
                v2[i] = x + __shfl_xor_sync(0xffffffffu, o, 4);
            }
        }
        float y;
        {
            bool b1 = (l & 2) != 0;
            float x = b1 ? v2[1] : v2[0];
            float o = b1 ? v2[0] : v2[1];
            y = x + __shfl_xor_sync(0xffffffffu, o, 2);
            y += __shfl_xor_sync(0xffffffffu, y, 1);
        }
        // lane l holds complete slice-partial of value (l>>1)
        if (!(l & 1)) sRed[(w << 4) + (l >> 1)] = y;
        __syncthreads();

        // ===== gate lanes combine slice partials + activations =====
        float pre_raw = 0.f;
        if (l < 8) {
            int L = l >> 2;               // 0 = layer0, 1 = layer1
            int v = (L << 3) + w;         // value index: layer*8 + elem j
            pre_raw = sRed[(gl << 4) + v] + sRed[((gl + 4) << 4) + v];
        }
        float pre = pre_raw + ((l & 4) ? bs1v : xv);
        float kx  = (gl == 2) ? 2.f * pre : pre;        // tanh needs 2x
        float ev  = __expf(-kx);
        float rv  = __fdividef(1.f, 1.f + ev);
        float act = (gl == 2) ? fmaf(2.f, rv, -1.f) : rv;

        int base = l & 4;
        float iv = __shfl_sync(0xffffffffu, act, base + 0);
        float fv = __shfl_sync(0xffffffffu, act, base + 1);
        float gv = __shfl_sync(0xffffffffu, act, base + 2);
        float ov = __shfl_sync(0xffffffffu, act, base + 3);

        float h1n = 0.f;
        if (l == 0 && s < TT) {                   // layer 0: h0_s
            c0 = fmaf(fv, c0, iv * gv);
            sPub[w] = ov * fast_tanh(c0);
        }
        if (l == 4 && s >= 2) {                   // layer 1: h1_{s-2}
            c1 = fmaf(fv, c1, iv * gv);
            h1n = ov * fast_tanh(c1);
            sPub[8 + w] = h1n;
        }
        __syncthreads();

        // ===== publish (tid 0 only -> release covers its own stores) =====
        if (tid == 0) {
            float4 p0 = *(const float4*)&sPub[0];
            float4 p1 = *(const float4*)&sPub[4];
            float4 q0 = *(const float4*)&sPub[8];
            float4 q1 = *(const float4*)&sPub[12];
            float4* dst = (float4*)g_pubH[(s + 1) & 1];
            __stcg(dst + 2 * b,           p0);
            __stcg(dst + 2 * b + 1,       p1);
            __stcg(dst + 256 + 2 * b,     q0);
            __stcg(dst + 256 + 2 * b + 1, q1);
            asm volatile("st.release.gpu.global.u32 [%0], %1;"
                         :: "l"(&g_flag[b]), "r"((unsigned)(s + 1)) : "memory");
        }

        // ===== h1 history (off the release path, lane 4) =====
        if (l == 4 && s >= 2) {
            __stcg(&g_h1[(size_t)(s - 2) * HDIM + e], h1n);
        }

        xv = nxv;
    }
}

// ---------------- FC + log_softmax ----------------
__global__ __launch_bounds__(128) void fc_logsoftmax_kernel(
    const float* __restrict__ fcw,    // [109][1024]
    const float* __restrict__ fcb,    // [109]
    float* __restrict__ out)          // [T][109]
{
    __shared__ float sH[8 * 1024];
    __shared__ float sL[8][112];
    __shared__ float sLse[8];
    int t0 = blockIdx.x * 8;
    int tid = threadIdx.x;

    const float4* hg = (const float4*)(g_h1 + (size_t)t0 * HDIM);
    float4* sH4 = (float4*)sH;
#pragma unroll
    for (int q = 0; q < 16; q++) sH4[tid + 128 * q] = __ldg(hg + tid + 128 * q);
    __syncthreads();

    if (tid < INDIM) {
        float acc[8];
#pragma unroll
        for (int i = 0; i < 8; i++) acc[i] = 0.f;
        const float4* w4 = (const float4*)(fcw + (size_t)tid * HDIM);
        for (int k4 = 0; k4 < 256; k4++) {
            float4 w = __ldg(w4 + k4);
#pragma unroll
            for (int tt = 0; tt < 8; tt++) {
                float4 hv = sH4[tt * 256 + k4];
                acc[tt] = fmaf(w.x, hv.x,
                          fmaf(w.y, hv.y,
                          fmaf(w.z, hv.z,
                          fmaf(w.w, hv.w, acc[tt]))));
            }
        }
        float bb = __ldg(&fcb[tid]);
#pragma unroll
        for (int tt = 0; tt < 8; tt++) sL[tt][tid] = acc[tt] + bb;
    }
    __syncthreads();

    if (tid < 8) {
        float m = -1e30f;
        for (int n = 0; n < INDIM; n++) m = fmaxf(m, sL[tid][n]);
        float s = 0.f;
        for (int n = 0; n < INDIM; n++) s += expf(sL[tid][n] - m);
        sLse[tid] = m + logf(s);
    }
    __syncthreads();

    for (int idx = tid; idx < 8 * INDIM; idx += 128) {
        int tt = idx / INDIM, n = idx - tt * INDIM;
        out[(size_t)(t0 + tt) * INDIM + n] = sL[tt][n] - sLse[tt];
    }
}

// ---------------- launcher ----------------
extern "C" void kernel_launch(void* const* d_in, const int* in_sizes, int n_in,
                              void* d_out, int out_size) {
    const float* input = (const float*)d_in[0];
    const float* W_ih0 = (const float*)d_in[1];
    const float* W_hh0 = (const float*)d_in[2];
    const float* b_ih0 = (const float*)d_in[3];
    const float* b_hh0 = (const float*)d_in[4];
    const float* W_ih1 = (const float*)d_in[5];
    const float* W_hh1 = (const float*)d_in[6];
    const float* b_ih1 = (const float*)d_in[7];
    const float* b_hh1 = (const float*)d_in[8];
    const float* fc_w  = (const float*)d_in[9];
    const float* fc_b  = (const float*)d_in[10];
    float* out = (float*)d_out;

    cudaFuncSetAttribute(lstm_fused_kernel,
                         cudaFuncAttributeMaxDynamicSharedMemorySize, FUS_SMEM);

    // xp0 = input @ W_ih0^T + b_ih0 + b_hh0
    gemm_xproj_small<<<dim3(TT / 64, GDIM / 32), 256>>>(input, W_ih0, b_ih0, b_hh0);

    // fused 2-layer recurrence -> g_h1
    reset_state_kernel<<<1, 1024>>>();
    lstm_fused_kernel<<<NBLK, 256, FUS_SMEM>>>(W_hh0, W_ih1, W_hh1, b_ih1, b_hh1);

    // logits + log_softmax
    fc_logsoftmax_kernel<<<TT / 8, 128>>>(fc_w, fc_b, out);
}